// round 1
// baseline (speedup 1.0000x reference)
#include <cuda_runtime.h>
#include <cuda_bf16.h>
#include <cfloat>
#include <math.h>

// ---------------------------------------------------------------------------
// Problem constants
//   z2: (8,128,24,24)  y1: (8,192,96,96)
//   cat = concat(upsample4x(z2), y1) : (8,320,96,96)
//   sigma = relu(c5(relu(c5(relu(c5(cat,ws1)),ws2)),ws3))        -> (8,576,96,96)
//   means = c5(lrelu(c5(lrelu(c5(cat,wm1)),wm2)),wm3)            -> (8,576,96,96)
//   w     = softmax_K( c1x1( lrelu( maxHW( c5(lrelu(c5(cat,ww1)),ww2) ))))
// Output packing assumed: [sigma | means | weights]
// ---------------------------------------------------------------------------
#define BATCH 8
#define CH_Z 128
#define CH_Y 192
#define CH_CAT 320
#define CH_N 128
#define CH_MK 576
#define HW 96
#define HW2 (HW*HW)

typedef unsigned long long ull;

// -------------------- scratch (static device globals; no allocs) ------------
__device__ float g_cat[BATCH * CH_CAT * HW2];   // 94.4 MB
__device__ float g_t1 [BATCH * CH_N   * HW2];   // 37.7 MB
__device__ float g_t2 [BATCH * CH_N   * HW2];   // 37.7 MB
__device__ float g_pool[BATCH * CH_MK];         // pooled max

// -------------------- f32x2 helpers -----------------------------------------
__device__ __forceinline__ ull pk2(float a, float b) {
    ull r; asm("mov.b64 %0, {%1, %2};" : "=l"(r) : "f"(a), "f"(b)); return r;
}
__device__ __forceinline__ void upk2(ull v, float& a, float& b) {
    asm("mov.b64 {%0, %1}, %2;" : "=f"(a), "=f"(b) : "l"(v));
}
__device__ __forceinline__ void ffma2(ull& d, ull a, ull b) {
    asm("fma.rn.f32x2 %0, %1, %2, %0;" : "+l"(d) : "l"(a), "l"(b));
}

__device__ __forceinline__ void atomicMaxFloat(float* addr, float v) {
    if (v >= 0.0f) atomicMax((int*)addr, __float_as_int(v));
    else           atomicMin((unsigned int*)addr, __float_as_uint(v));
}

// -------------------- upsample + concat -------------------------------------
__global__ void upsample_concat_kernel(const float* __restrict__ z2,
                                       const float* __restrict__ y1) {
    int idx = blockIdx.x * blockDim.x + threadIdx.x;
    const int total = BATCH * CH_CAT * HW2;
    if (idx >= total) return;
    int x = idx % HW;
    int y = (idx / HW) % HW;
    int c = (idx / HW2) % CH_CAT;
    int n = idx / (CH_CAT * HW2);
    if (c >= CH_Z) {
        g_cat[idx] = y1[((n * CH_Y + (c - CH_Z)) * HW + y) * HW + x];
    } else {
        // linspace(0, 23, 96): f = i*23/95
        float fy = (float)((double)y * 23.0 / 95.0);
        float fx = (float)((double)x * 23.0 / 95.0);
        int y0 = (int)floorf(fy); int y1i = min(y0 + 1, 23);
        int x0 = (int)floorf(fx); int x1i = min(x0 + 1, 23);
        float wy = fy - (float)y0;
        float wx = fx - (float)x0;
        const float* src = z2 + ((n * CH_Z + c) * 24) * 24;
        float v00 = src[y0 * 24 + x0], v01 = src[y0 * 24 + x1i];
        float v10 = src[y1i * 24 + x0], v11 = src[y1i * 24 + x1i];
        float r0 = v00 * (1.f - wx) + v01 * wx;
        float r1 = v10 * (1.f - wx) + v11 * wx;
        g_cat[idx] = r0 * (1.f - wy) + r1 * wy;
    }
}

// -------------------- init pooled max ---------------------------------------
__global__ void init_pool_kernel() {
    int i = blockIdx.x * blockDim.x + threadIdx.x;
    if (i < BATCH * CH_MK) g_pool[i] = -FLT_MAX;
}

// -------------------- direct conv 5x5, pad 2 --------------------------------
// Block: 64 out-channels x 16x16 spatial tile, one batch image.
// 256 threads: og = tid/64 (16 oc each), sp = tid%64 -> (sy,sx) in 8x8,
// each thread computes 2x2 output pixels for its 16 oc.
// act: 0=none 1=relu 2=lrelu. maxout!=null => no store, reduce max per (n,oc).
#define CK 4
__global__ __launch_bounds__(256, 2)
void conv5x5_kernel(const float* __restrict__ in, int cin,
                    const float* __restrict__ w, const float* __restrict__ bias,
                    float* __restrict__ out, int cout,
                    int act, float* __restrict__ maxout) {
    extern __shared__ unsigned char smem_raw[];
    float  (*s_in)[20][21]  = (float (*)[20][21])smem_raw;                 // CK*20*21*4 = 6720B
    float2 (*s_w2)[25][64]  = (float2 (*)[25][64])(smem_raw + CK*20*21*4); // CK*25*64*8 = 51200B

    const int tid = threadIdx.x;
    const int og  = tid >> 6;          // 0..3
    const int sp  = tid & 63;
    const int sy  = sp >> 3;           // 0..7
    const int sx  = sp & 7;            // 0..7
    const int tIdx = blockIdx.x;       // 0..35
    const int ty = tIdx / 6, tx = tIdx % 6;
    const int ocb = blockIdx.y * 64;
    const int n   = blockIdx.z;
    const int y0t = ty * 16, x0t = tx * 16;

    ull acc0[16], acc1[16];
    #pragma unroll
    for (int o = 0; o < 16; o++) { acc0[o] = 0ull; acc1[o] = 0ull; }

    for (int cb = 0; cb < cin; cb += CK) {
        // load input patch CK x 20 x 20 (pad with zeros)
        for (int i = tid; i < CK * 400; i += 256) {
            int c = i / 400, r = i % 400;
            int py = r / 20, px = r % 20;
            int gy = y0t + py - 2, gx = x0t + px - 2;
            float v = 0.0f;
            if (gy >= 0 && gy < HW && gx >= 0 && gx < HW)
                v = in[((n * cin + cb + c) * HW + gy) * HW + gx];
            s_in[c][py][px] = v;
        }
        // load weights, duplicated into float2 lanes
        for (int i = tid; i < CK * 25 * 64; i += 256) {
            int oc = i & 63, tap = (i >> 6) % 25, c = i / 1600;
            float wv = w[((ocb + oc) * cin + cb + c) * 25 + tap];
            s_w2[c][tap][oc] = make_float2(wv, wv);
        }
        __syncthreads();

        #pragma unroll
        for (int c = 0; c < CK; c++) {
            #pragma unroll
            for (int ky = 0; ky < 5; ky++) {
                const int yy = 2 * sy + ky;
                float r0[6], r1[6];
                #pragma unroll
                for (int j = 0; j < 6; j++) {
                    r0[j] = s_in[c][yy][2 * sx + j];
                    r1[j] = s_in[c][yy + 1][2 * sx + j];
                }
                #pragma unroll
                for (int kx = 0; kx < 5; kx++) {
                    ull iv0 = pk2(r0[kx], r0[kx + 1]);
                    ull iv1 = pk2(r1[kx], r1[kx + 1]);
                    const int tap = ky * 5 + kx;
                    #pragma unroll
                    for (int o = 0; o < 16; o++) {
                        ull wv = *reinterpret_cast<const ull*>(&s_w2[c][tap][og * 16 + o]);
                        ffma2(acc0[o], iv0, wv);
                        ffma2(acc1[o], iv1, wv);
                    }
                }
            }
        }
        __syncthreads();
    }

    const int oc0 = ocb + og * 16;
    if (maxout == nullptr) {
        const int oy0 = y0t + 2 * sy, ox0 = x0t + 2 * sx;
        #pragma unroll
        for (int o = 0; o < 16; o++) {
            float a00, a01, a10, a11;
            upk2(acc0[o], a00, a01);
            upk2(acc1[o], a10, a11);
            float bv = bias[oc0 + o];
            a00 += bv; a01 += bv; a10 += bv; a11 += bv;
            if (act == 1) {
                a00 = fmaxf(a00, 0.f); a01 = fmaxf(a01, 0.f);
                a10 = fmaxf(a10, 0.f); a11 = fmaxf(a11, 0.f);
            } else if (act == 2) {
                a00 = a00 >= 0.f ? a00 : 0.01f * a00;
                a01 = a01 >= 0.f ? a01 : 0.01f * a01;
                a10 = a10 >= 0.f ? a10 : 0.01f * a10;
                a11 = a11 >= 0.f ? a11 : 0.01f * a11;
            }
            float* op = out + ((size_t)(n * cout + oc0 + o) * HW + oy0) * HW + ox0;
            *reinterpret_cast<float2*>(op)      = make_float2(a00, a01);
            *reinterpret_cast<float2*>(op + HW) = make_float2(a10, a11);
        }
    } else {
        const int lane = tid & 31;
        #pragma unroll
        for (int o = 0; o < 16; o++) {
            float a00, a01, a10, a11;
            upk2(acc0[o], a00, a01);
            upk2(acc1[o], a10, a11);
            float m = fmaxf(fmaxf(a00, a01), fmaxf(a10, a11));
            #pragma unroll
            for (int d = 16; d; d >>= 1)
                m = fmaxf(m, __shfl_xor_sync(0xffffffffu, m, d));
            if (lane == 0) atomicMaxFloat(&maxout[n * cout + oc0 + o], m);
        }
    }
}

// -------------------- final: bias+lrelu pooled -> 1x1 conv -> softmax --------
__global__ void final_kernel(const float* __restrict__ bw2,
                             const float* __restrict__ ww3,
                             const float* __restrict__ bw3,
                             float* __restrict__ out_w) {
    __shared__ float sp_[CH_MK];
    __shared__ float sv_[CH_MK];
    const int c = threadIdx.x;
    const int n = blockIdx.x;
    float pv = g_pool[n * CH_MK + c] + bw2[c];
    sp_[c] = pv >= 0.f ? pv : 0.01f * pv;
    __syncthreads();
    float s = bw3[c];
    const float* wr = ww3 + c * CH_MK;
    for (int i = 0; i < CH_MK; i++) s += wr[i] * sp_[i];
    sv_[c] = s;
    __syncthreads();
    const int m = c % 192;
    float e0 = sv_[m], e1 = sv_[m + 192], e2 = sv_[m + 384];
    float mx = fmaxf(e0, fmaxf(e1, e2));
    float den = expf(e0 - mx) + expf(e1 - mx) + expf(e2 - mx);
    out_w[n * CH_MK + c] = expf(sv_[c] - mx) / den;
}

// -------------------- launch ------------------------------------------------
extern "C" void kernel_launch(void* const* d_in, const int* in_sizes, int n_in,
                              void* d_out, int out_size) {
    const float* z2  = (const float*)d_in[0];
    const float* y1  = (const float*)d_in[1];
    const float* ws1 = (const float*)d_in[2];  const float* bs1 = (const float*)d_in[3];
    const float* ws2 = (const float*)d_in[4];  const float* bs2 = (const float*)d_in[5];
    const float* ws3 = (const float*)d_in[6];  const float* bs3 = (const float*)d_in[7];
    const float* wm1 = (const float*)d_in[8];  const float* bm1 = (const float*)d_in[9];
    const float* wm2 = (const float*)d_in[10]; const float* bm2 = (const float*)d_in[11];
    const float* wm3 = (const float*)d_in[12]; const float* bm3 = (const float*)d_in[13];
    const float* ww1 = (const float*)d_in[14]; const float* bw1 = (const float*)d_in[15];
    const float* ww2 = (const float*)d_in[16]; const float* bw2 = (const float*)d_in[17];
    const float* ww3 = (const float*)d_in[18]; const float* bw3 = (const float*)d_in[19];

    float* out = (float*)d_out;
    const size_t SIG_OFF = 0;
    const size_t MEAN_OFF = (size_t)BATCH * CH_MK * HW2;       // 42467328
    const size_t W_OFF    = 2 * MEAN_OFF;                      // 84934656

    void* p;
    cudaGetSymbolAddress(&p, g_cat); float* cat = (float*)p;
    cudaGetSymbolAddress(&p, g_t1);  float* t1  = (float*)p;
    cudaGetSymbolAddress(&p, g_t2);  float* t2  = (float*)p;

    const int smem = CK * 20 * 21 * 4 + CK * 25 * 64 * 8;  // 57920
    cudaFuncSetAttribute(conv5x5_kernel,
                         cudaFuncAttributeMaxDynamicSharedMemorySize, smem);

    // upsample + concat
    {
        int total = BATCH * CH_CAT * HW2;
        upsample_concat_kernel<<<(total + 255) / 256, 256>>>(z2, y1);
    }
    init_pool_kernel<<<(BATCH * CH_MK + 255) / 256, 256>>>();

    dim3 blk(256);
    dim3 g128(36, CH_N / 64, BATCH);
    dim3 g576(36, CH_MK / 64, BATCH);

    // sigma branch (relu, relu, relu)
    conv5x5_kernel<<<g128, blk, smem>>>(cat, CH_CAT, ws1, bs1, t1, CH_N, 1, nullptr);
    conv5x5_kernel<<<g128, blk, smem>>>(t1, CH_N, ws2, bs2, t2, CH_N, 1, nullptr);
    conv5x5_kernel<<<g576, blk, smem>>>(t2, CH_N, ws3, bs3, out + SIG_OFF, CH_MK, 1, nullptr);

    // means branch (lrelu, lrelu, none)
    conv5x5_kernel<<<g128, blk, smem>>>(cat, CH_CAT, wm1, bm1, t1, CH_N, 2, nullptr);
    conv5x5_kernel<<<g128, blk, smem>>>(t1, CH_N, wm2, bm2, t2, CH_N, 2, nullptr);
    conv5x5_kernel<<<g576, blk, smem>>>(t2, CH_N, wm3, bm3, out + MEAN_OFF, CH_MK, 0, nullptr);

    // weights branch (lrelu, then fused max-pool)
    conv5x5_kernel<<<g128, blk, smem>>>(cat, CH_CAT, ww1, bw1, t1, CH_N, 2, nullptr);
    {
        void* pp; cudaGetSymbolAddress(&pp, g_pool);
        conv5x5_kernel<<<g576, blk, smem>>>(t1, CH_N, ww2, nullptr, nullptr, CH_MK, 0, (float*)pp);
        final_kernel<<<BATCH, CH_MK>>>(bw2, ww3, bw3, out + W_OFF);
    }
}

// round 2
// speedup vs baseline: 1.0004x; 1.0004x over previous
#include <cuda_runtime.h>
#include <cuda_bf16.h>
#include <cfloat>
#include <math.h>

// ---------------------------------------------------------------------------
// Problem constants
//   z2: (8,128,24,24)  y1: (8,192,96,96)
//   cat = concat(upsample4x(z2), y1) : (8,320,96,96)
//   sigma = relu(c5(relu(c5(relu(c5(cat,ws1)),ws2)),ws3))        -> (8,576,96,96)
//   means = c5(lrelu(c5(lrelu(c5(cat,wm1)),wm2)),wm3)            -> (8,576,96,96)
//   w     = softmax_K( c1x1( lrelu( maxHW( c5(lrelu(c5(cat,ww1)),ww2) ))))
// Output packing assumed: [sigma | means | weights]
// ---------------------------------------------------------------------------
#define BATCH 8
#define CH_Z 128
#define CH_Y 192
#define CH_CAT 320
#define CH_N 128
#define CH_MK 576
#define HW 96
#define HW2 (HW*HW)

typedef unsigned long long ull;

// -------------------- scratch (static device globals; no allocs) ------------
__device__ float g_cat[BATCH * CH_CAT * HW2];   // 94.4 MB
__device__ float g_t1 [BATCH * CH_N   * HW2];   // 37.7 MB
__device__ float g_t2 [BATCH * CH_N   * HW2];   // 37.7 MB
__device__ float g_pool[BATCH * CH_MK];         // pooled max

// -------------------- f32x2 helpers -----------------------------------------
__device__ __forceinline__ ull pk2(float a, float b) {
    ull r; asm("mov.b64 %0, {%1, %2};" : "=l"(r) : "f"(a), "f"(b)); return r;
}
__device__ __forceinline__ void upk2(ull v, float& a, float& b) {
    asm("mov.b64 {%0, %1}, %2;" : "=f"(a), "=f"(b) : "l"(v));
}
__device__ __forceinline__ void ffma2(ull& d, ull a, ull b) {
    asm("fma.rn.f32x2 %0, %1, %2, %0;" : "+l"(d) : "l"(a), "l"(b));
}

__device__ __forceinline__ void atomicMaxFloat(float* addr, float v) {
    if (v >= 0.0f) atomicMax((int*)addr, __float_as_int(v));
    else           atomicMin((unsigned int*)addr, __float_as_uint(v));
}

// -------------------- upsample + concat -------------------------------------
__global__ void upsample_concat_kernel(const float* __restrict__ z2,
                                       const float* __restrict__ y1) {
    int idx = blockIdx.x * blockDim.x + threadIdx.x;
    const int total = BATCH * CH_CAT * HW2;
    if (idx >= total) return;
    int x = idx % HW;
    int y = (idx / HW) % HW;
    int c = (idx / HW2) % CH_CAT;
    int n = idx / (CH_CAT * HW2);
    if (c >= CH_Z) {
        g_cat[idx] = y1[((n * CH_Y + (c - CH_Z)) * HW + y) * HW + x];
    } else {
        // linspace(0, 23, 96): f = i*23/95
        float fy = (float)((double)y * 23.0 / 95.0);
        float fx = (float)((double)x * 23.0 / 95.0);
        int y0 = (int)floorf(fy); int y1i = min(y0 + 1, 23);
        int x0 = (int)floorf(fx); int x1i = min(x0 + 1, 23);
        float wy = fy - (float)y0;
        float wx = fx - (float)x0;
        const float* src = z2 + ((n * CH_Z + c) * 24) * 24;
        float v00 = src[y0 * 24 + x0], v01 = src[y0 * 24 + x1i];
        float v10 = src[y1i * 24 + x0], v11 = src[y1i * 24 + x1i];
        float r0 = v00 * (1.f - wx) + v01 * wx;
        float r1 = v10 * (1.f - wx) + v11 * wx;
        g_cat[idx] = r0 * (1.f - wy) + r1 * wy;
    }
}

// -------------------- init pooled max ---------------------------------------
__global__ void init_pool_kernel() {
    int i = blockIdx.x * blockDim.x + threadIdx.x;
    if (i < BATCH * CH_MK) g_pool[i] = -FLT_MAX;
}

// -------------------- direct conv 5x5, pad 2 --------------------------------
// Block: 64 out-channels x 16x16 spatial tile, one batch image.
// 256 threads: og = tid/64 (16 oc each), sp = tid%64 -> (sy,sx) in 8x8,
// each thread computes 2x2 output pixels for its 16 oc.
// act: 0=none 1=relu 2=lrelu. maxout!=null => no store, reduce max per (n,oc).
#define CK 4
__global__ __launch_bounds__(256, 2)
void conv5x5_kernel(const float* __restrict__ in, int cin,
                    const float* __restrict__ w, const float* __restrict__ bias,
                    float* __restrict__ out, int cout,
                    int act, float* __restrict__ maxout) {
    extern __shared__ unsigned char smem_raw[];
    float  (*s_in)[20][21]  = (float (*)[20][21])smem_raw;                 // CK*20*21*4 = 6720B
    float2 (*s_w2)[25][64]  = (float2 (*)[25][64])(smem_raw + CK*20*21*4); // CK*25*64*8 = 51200B

    const int tid = threadIdx.x;
    const int og  = tid >> 6;          // 0..3
    const int sp  = tid & 63;
    const int sy  = sp >> 3;           // 0..7
    const int sx  = sp & 7;            // 0..7
    const int tIdx = blockIdx.x;       // 0..35
    const int ty = tIdx / 6, tx = tIdx % 6;
    const int ocb = blockIdx.y * 64;
    const int n   = blockIdx.z;
    const int y0t = ty * 16, x0t = tx * 16;

    ull acc0[16], acc1[16];
    #pragma unroll
    for (int o = 0; o < 16; o++) { acc0[o] = 0ull; acc1[o] = 0ull; }

    for (int cb = 0; cb < cin; cb += CK) {
        // load input patch CK x 20 x 20 (pad with zeros)
        for (int i = tid; i < CK * 400; i += 256) {
            int c = i / 400, r = i % 400;
            int py = r / 20, px = r % 20;
            int gy = y0t + py - 2, gx = x0t + px - 2;
            float v = 0.0f;
            if (gy >= 0 && gy < HW && gx >= 0 && gx < HW)
                v = in[((n * cin + cb + c) * HW + gy) * HW + gx];
            s_in[c][py][px] = v;
        }
        // load weights, duplicated into float2 lanes
        for (int i = tid; i < CK * 25 * 64; i += 256) {
            int oc = i & 63, tap = (i >> 6) % 25, c = i / 1600;
            float wv = w[((ocb + oc) * cin + cb + c) * 25 + tap];
            s_w2[c][tap][oc] = make_float2(wv, wv);
        }
        __syncthreads();

        #pragma unroll
        for (int c = 0; c < CK; c++) {
            #pragma unroll
            for (int ky = 0; ky < 5; ky++) {
                const int yy = 2 * sy + ky;
                float r0[6], r1[6];
                #pragma unroll
                for (int j = 0; j < 6; j++) {
                    r0[j] = s_in[c][yy][2 * sx + j];
                    r1[j] = s_in[c][yy + 1][2 * sx + j];
                }
                #pragma unroll
                for (int kx = 0; kx < 5; kx++) {
                    ull iv0 = pk2(r0[kx], r0[kx + 1]);
                    ull iv1 = pk2(r1[kx], r1[kx + 1]);
                    const int tap = ky * 5 + kx;
                    #pragma unroll
                    for (int o = 0; o < 16; o++) {
                        ull wv = *reinterpret_cast<const ull*>(&s_w2[c][tap][og * 16 + o]);
                        ffma2(acc0[o], iv0, wv);
                        ffma2(acc1[o], iv1, wv);
                    }
                }
            }
        }
        __syncthreads();
    }

    const int oc0 = ocb + og * 16;
    if (maxout == nullptr) {
        const int oy0 = y0t + 2 * sy, ox0 = x0t + 2 * sx;
        #pragma unroll
        for (int o = 0; o < 16; o++) {
            float a00, a01, a10, a11;
            upk2(acc0[o], a00, a01);
            upk2(acc1[o], a10, a11);
            float bv = bias[oc0 + o];
            a00 += bv; a01 += bv; a10 += bv; a11 += bv;
            if (act == 1) {
                a00 = fmaxf(a00, 0.f); a01 = fmaxf(a01, 0.f);
                a10 = fmaxf(a10, 0.f); a11 = fmaxf(a11, 0.f);
            } else if (act == 2) {
                a00 = a00 >= 0.f ? a00 : 0.01f * a00;
                a01 = a01 >= 0.f ? a01 : 0.01f * a01;
                a10 = a10 >= 0.f ? a10 : 0.01f * a10;
                a11 = a11 >= 0.f ? a11 : 0.01f * a11;
            }
            float* op = out + ((size_t)(n * cout + oc0 + o) * HW + oy0) * HW + ox0;
            *reinterpret_cast<float2*>(op)      = make_float2(a00, a01);
            *reinterpret_cast<float2*>(op + HW) = make_float2(a10, a11);
        }
    } else {
        const int lane = tid & 31;
        #pragma unroll
        for (int o = 0; o < 16; o++) {
            float a00, a01, a10, a11;
            upk2(acc0[o], a00, a01);
            upk2(acc1[o], a10, a11);
            float m = fmaxf(fmaxf(a00, a01), fmaxf(a10, a11));
            #pragma unroll
            for (int d = 16; d; d >>= 1)
                m = fmaxf(m, __shfl_xor_sync(0xffffffffu, m, d));
            if (lane == 0) atomicMaxFloat(&maxout[n * cout + oc0 + o], m);
        }
    }
}

// -------------------- final: bias+lrelu pooled -> 1x1 conv -> softmax --------
__global__ void final_kernel(const float* __restrict__ bw2,
                             const float* __restrict__ ww3,
                             const float* __restrict__ bw3,
                             float* __restrict__ out_w) {
    __shared__ float sp_[CH_MK];
    __shared__ float sv_[CH_MK];
    const int c = threadIdx.x;
    const int n = blockIdx.x;
    float pv = g_pool[n * CH_MK + c] + bw2[c];
    sp_[c] = pv >= 0.f ? pv : 0.01f * pv;
    __syncthreads();
    float s = bw3[c];
    const float* wr = ww3 + c * CH_MK;
    for (int i = 0; i < CH_MK; i++) s += wr[i] * sp_[i];
    sv_[c] = s;
    __syncthreads();
    const int m = c % 192;
    float e0 = sv_[m], e1 = sv_[m + 192], e2 = sv_[m + 384];
    float mx = fmaxf(e0, fmaxf(e1, e2));
    float den = expf(e0 - mx) + expf(e1 - mx) + expf(e2 - mx);
    out_w[n * CH_MK + c] = expf(sv_[c] - mx) / den;
}

// -------------------- launch ------------------------------------------------
extern "C" void kernel_launch(void* const* d_in, const int* in_sizes, int n_in,
                              void* d_out, int out_size) {
    const float* z2  = (const float*)d_in[0];
    const float* y1  = (const float*)d_in[1];
    const float* ws1 = (const float*)d_in[2];  const float* bs1 = (const float*)d_in[3];
    const float* ws2 = (const float*)d_in[4];  const float* bs2 = (const float*)d_in[5];
    const float* ws3 = (const float*)d_in[6];  const float* bs3 = (const float*)d_in[7];
    const float* wm1 = (const float*)d_in[8];  const float* bm1 = (const float*)d_in[9];
    const float* wm2 = (const float*)d_in[10]; const float* bm2 = (const float*)d_in[11];
    const float* wm3 = (const float*)d_in[12]; const float* bm3 = (const float*)d_in[13];
    const float* ww1 = (const float*)d_in[14]; const float* bw1 = (const float*)d_in[15];
    const float* ww2 = (const float*)d_in[16]; const float* bw2 = (const float*)d_in[17];
    const float* ww3 = (const float*)d_in[18]; const float* bw3 = (const float*)d_in[19];

    float* out = (float*)d_out;
    const size_t SIG_OFF = 0;
    const size_t MEAN_OFF = (size_t)BATCH * CH_MK * HW2;       // 42467328
    const size_t W_OFF    = 2 * MEAN_OFF;                      // 84934656

    void* p;
    cudaGetSymbolAddress(&p, g_cat); float* cat = (float*)p;
    cudaGetSymbolAddress(&p, g_t1);  float* t1  = (float*)p;
    cudaGetSymbolAddress(&p, g_t2);  float* t2  = (float*)p;

    const int smem = CK * 20 * 21 * 4 + CK * 25 * 64 * 8;  // 57920
    cudaFuncSetAttribute(conv5x5_kernel,
                         cudaFuncAttributeMaxDynamicSharedMemorySize, smem);

    // upsample + concat
    {
        int total = BATCH * CH_CAT * HW2;
        upsample_concat_kernel<<<(total + 255) / 256, 256>>>(z2, y1);
    }
    init_pool_kernel<<<(BATCH * CH_MK + 255) / 256, 256>>>();

    dim3 blk(256);
    dim3 g128(36, CH_N / 64, BATCH);
    dim3 g576(36, CH_MK / 64, BATCH);

    // sigma branch (relu, relu, relu)
    conv5x5_kernel<<<g128, blk, smem>>>(cat, CH_CAT, ws1, bs1, t1, CH_N, 1, nullptr);
    conv5x5_kernel<<<g128, blk, smem>>>(t1, CH_N, ws2, bs2, t2, CH_N, 1, nullptr);
    conv5x5_kernel<<<g576, blk, smem>>>(t2, CH_N, ws3, bs3, out + SIG_OFF, CH_MK, 1, nullptr);

    // means branch (lrelu, lrelu, none)
    conv5x5_kernel<<<g128, blk, smem>>>(cat, CH_CAT, wm1, bm1, t1, CH_N, 2, nullptr);
    conv5x5_kernel<<<g128, blk, smem>>>(t1, CH_N, wm2, bm2, t2, CH_N, 2, nullptr);
    conv5x5_kernel<<<g576, blk, smem>>>(t2, CH_N, wm3, bm3, out + MEAN_OFF, CH_MK, 0, nullptr);

    // weights branch (lrelu, then fused max-pool)
    conv5x5_kernel<<<g128, blk, smem>>>(cat, CH_CAT, ww1, bw1, t1, CH_N, 2, nullptr);
    {
        void* pp; cudaGetSymbolAddress(&pp, g_pool);
        conv5x5_kernel<<<g576, blk, smem>>>(t1, CH_N, ww2, nullptr, nullptr, CH_MK, 0, (float*)pp);
        final_kernel<<<BATCH, CH_MK>>>(bw2, ww3, bw3, out + W_OFF);
    }
}

// round 3
// speedup vs baseline: 1.0775x; 1.0770x over previous
#include <cuda_runtime.h>
#include <cuda_bf16.h>
#include <cfloat>
#include <math.h>

// ---------------------------------------------------------------------------
//   z2: (8,128,24,24)  y1: (8,192,96,96)
//   cat = concat(upsample4x(z2), y1) : (8,320,96,96)
//   sigma = relu(c5(relu(c5(relu(c5(cat,ws1)),ws2)),ws3))        -> (8,576,96,96)
//   means = c5(lrelu(c5(lrelu(c5(cat,wm1)),wm2)),wm3)            -> (8,576,96,96)
//   w     = softmax_K( c1x1( lrelu( maxHW( c5(lrelu(c5(cat,ww1)),ww2) ))))
// Output packing: [sigma | means | weights]
// ---------------------------------------------------------------------------
#define BATCH 8
#define CH_Z 128
#define CH_Y 192
#define CH_CAT 320
#define CH_N 128
#define CH_MK 576
#define HW 96
#define HW2 (HW*HW)

typedef unsigned long long ull;

// -------------------- scratch (static device globals; no allocs) ------------
__device__ float g_cat[BATCH * CH_CAT * HW2];
__device__ float g_t1 [BATCH * CH_N   * HW2];
__device__ float g_t2 [BATCH * CH_N   * HW2];
__device__ float g_pool[BATCH * CH_MK];

// -------------------- f32x2 helpers -----------------------------------------
__device__ __forceinline__ void upk2(ull v, float& a, float& b) {
    asm("mov.b64 {%0, %1}, %2;" : "=f"(a), "=f"(b) : "l"(v));
}
__device__ __forceinline__ void ffma2(ull& d, ull a, ull b) {
    asm("fma.rn.f32x2 %0, %1, %2, %0;" : "+l"(d) : "l"(a), "l"(b));
}
// pair (hi(a), lo(b)) -- straddling pair for odd kx; pure register-half repack
__device__ __forceinline__ ull oddpair(ull a, ull b) {
    ull r;
    asm("{ .reg .b32 al, ah, bl, bh;\n"
        "  mov.b64 {al, ah}, %1;\n"
        "  mov.b64 {bl, bh}, %2;\n"
        "  mov.b64 %0, {ah, bl}; }" : "=l"(r) : "l"(a), "l"(b));
    return r;
}

__device__ __forceinline__ void atomicMaxFloat(float* addr, float v) {
    if (v >= 0.0f) atomicMax((int*)addr, __float_as_int(v));
    else           atomicMin((unsigned int*)addr, __float_as_uint(v));
}

// -------------------- upsample + concat -------------------------------------
__global__ void upsample_concat_kernel(const float* __restrict__ z2,
                                       const float* __restrict__ y1) {
    int idx = blockIdx.x * blockDim.x + threadIdx.x;
    const int total = BATCH * CH_CAT * HW2;
    if (idx >= total) return;
    int x = idx % HW;
    int y = (idx / HW) % HW;
    int c = (idx / HW2) % CH_CAT;
    int n = idx / (CH_CAT * HW2);
    if (c >= CH_Z) {
        g_cat[idx] = y1[((n * CH_Y + (c - CH_Z)) * HW + y) * HW + x];
    } else {
        float fy = (float)((double)y * 23.0 / 95.0);
        float fx = (float)((double)x * 23.0 / 95.0);
        int y0 = (int)floorf(fy); int y1i = min(y0 + 1, 23);
        int x0 = (int)floorf(fx); int x1i = min(x0 + 1, 23);
        float wy = fy - (float)y0;
        float wx = fx - (float)x0;
        const float* src = z2 + ((n * CH_Z + c) * 24) * 24;
        float v00 = src[y0 * 24 + x0], v01 = src[y0 * 24 + x1i];
        float v10 = src[y1i * 24 + x0], v11 = src[y1i * 24 + x1i];
        float r0 = v00 * (1.f - wx) + v01 * wx;
        float r1 = v10 * (1.f - wx) + v11 * wx;
        g_cat[idx] = r0 * (1.f - wy) + r1 * wy;
    }
}

__global__ void init_pool_kernel() {
    int i = blockIdx.x * blockDim.x + threadIdx.x;
    if (i < BATCH * CH_MK) g_pool[i] = -FLT_MAX;
}

// -------------------- direct conv 5x5, pad 2 --------------------------------
// Block: 16 oc x 32x32 spatial, one image. 256 threads.
//   tid = og*64 + s;  og in [0,4): 4 oc each;  s: sx=8*(s&3), sy=2*(s>>2)
// Thread computes 4 oc x 2 rows x 8 cols. Rows register-resident as packed
// f32x2 (ull[6]); one new row-load per ky (rotation). Weights broadcast
// (uniform address per warp) via LDS.128 of duplicated float2.
#define CK 4
#define SPITCH 40                       // floats per smem input row (160B)
#define SIN_BYTES (CK * 36 * SPITCH * 4)        // 23040
#define SW_BYTES  (CK * 25 * 16 * 8)            // 12800
#define SMEM_TOTAL (SIN_BYTES + SW_BYTES)       // 35840

__device__ __forceinline__ void ldrow(ull R[6], const float* p) {
    const ulonglong2* q = reinterpret_cast<const ulonglong2*>(p);
    ulonglong2 a = q[0], b = q[1], c = q[2];
    R[0] = a.x; R[1] = a.y; R[2] = b.x; R[3] = b.y; R[4] = c.x; R[5] = c.y;
}

// T feeds accR0 (top out row), Bo feeds accR1 (bottom out row)
__device__ __forceinline__ void do_ky(ull accT[16], ull accB[16],
                                      const ull T[6], const ull Bo[6],
                                      const float2* __restrict__ swrow, int og) {
    #pragma unroll
    for (int kx = 0; kx < 5; kx++) {
        const ulonglong2* wp =
            reinterpret_cast<const ulonglong2*>(swrow + kx * 16 + og * 4);
        ulonglong2 wA = wp[0], wB = wp[1];
        ull w4[4] = { wA.x, wA.y, wB.x, wB.y };
        ull ivT[4], ivB[4];
        const int sft = kx >> 1;
        if ((kx & 1) == 0) {
            #pragma unroll
            for (int j = 0; j < 4; j++) { ivT[j] = T[j + sft]; ivB[j] = Bo[j + sft]; }
        } else {
            #pragma unroll
            for (int j = 0; j < 4; j++) {
                ivT[j] = oddpair(T[j + sft],  T[j + sft + 1]);
                ivB[j] = oddpair(Bo[j + sft], Bo[j + sft + 1]);
            }
        }
        #pragma unroll
        for (int o = 0; o < 4; o++) {
            #pragma unroll
            for (int j = 0; j < 4; j++) {
                ffma2(accT[o * 4 + j], ivT[j], w4[o]);
                ffma2(accB[o * 4 + j], ivB[j], w4[o]);
            }
        }
    }
}

__global__ __launch_bounds__(256, 2)
void conv5x5_kernel(const float* __restrict__ in, int cin,
                    const float* __restrict__ w, const float* __restrict__ bias,
                    float* __restrict__ out, int cout,
                    int act, float* __restrict__ maxout) {
    extern __shared__ unsigned char smem_raw[];
    float*  s_in = (float*)smem_raw;                    // [CK][36][SPITCH]
    float2* s_w  = (float2*)(smem_raw + SIN_BYTES);     // [CK][25][16]

    const int tid = threadIdx.x;
    const int og  = tid >> 6;              // 0..3 -> 4 oc each
    const int s   = tid & 63;
    const int x0  = 8 * (s & 3);           // 0,8,16,24
    const int y0  = 2 * (s >> 2);          // 0..30
    const int by  = blockIdx.x / 3, bx = blockIdx.x % 3;
    const int ocb = blockIdx.y * 16;
    const int n   = blockIdx.z;
    const int gy0 = by * 32, gx0 = bx * 32;

    ull accR0[16], accR1[16];
    #pragma unroll
    for (int i = 0; i < 16; i++) { accR0[i] = 0ull; accR1[i] = 0ull; }

    for (int cb = 0; cb < cin; cb += CK) {
        // ---- stage input patch CK x 36x36 (zero-padded) ----
        for (int i = tid; i < CK * 36 * 36; i += 256) {
            int c  = i / 1296, r = i % 1296;
            int py = r / 36,  px = r % 36;
            int gy = gy0 + py - 2, gx = gx0 + px - 2;
            float v = 0.0f;
            if (gy >= 0 && gy < HW && gx >= 0 && gx < HW)
                v = in[((n * cin + cb + c) * HW + gy) * HW + gx];
            s_in[(c * 36 + py) * SPITCH + px] = v;
        }
        // ---- stage weights, duplicated into float2 lanes ----
        for (int i = tid; i < CK * 25 * 16; i += 256) {
            int oc = i & 15, tap = (i >> 4) % 25, c = i / 400;
            float wv = w[((ocb + oc) * cin + cb + c) * 25 + tap];
            s_w[(c * 25 + tap) * 16 + oc] = make_float2(wv, wv);
        }
        __syncthreads();

        for (int c = 0; c < CK; c++) {
            const float*  rb  = s_in + (c * 36 + y0) * SPITCH + x0;
            const float2* swc = s_w + c * 25 * 16;
            ull A[6], B[6];
            ldrow(A, rb);                 // rel row 0
            ldrow(B, rb + SPITCH);        // rel row 1
            do_ky(accR0, accR1, A, B, swc + 0 * 80, og);   // ky=0: rows(0,1)
            ldrow(A, rb + 2 * SPITCH);
            do_ky(accR0, accR1, B, A, swc + 1 * 80, og);   // ky=1: rows(1,2)
            ldrow(B, rb + 3 * SPITCH);
            do_ky(accR0, accR1, A, B, swc + 2 * 80, og);   // ky=2: rows(2,3)
            ldrow(A, rb + 4 * SPITCH);
            do_ky(accR0, accR1, B, A, swc + 3 * 80, og);   // ky=3: rows(3,4)
            ldrow(B, rb + 5 * SPITCH);
            do_ky(accR0, accR1, A, B, swc + 4 * 80, og);   // ky=4: rows(4,5)
        }
        __syncthreads();
    }

    const int oc0 = ocb + og * 4;
    if (maxout == nullptr) {
        const int oy = gy0 + y0, ox = gx0 + x0;
        #pragma unroll
        for (int o = 0; o < 4; o++) {
            float bv = bias[oc0 + o];
            float* op = out + ((size_t)(n * cout + oc0 + o) * HW + oy) * HW + ox;
            #pragma unroll
            for (int j = 0; j < 4; j++) {
                float a0, a1, b0, b1;
                upk2(accR0[o * 4 + j], a0, a1);
                upk2(accR1[o * 4 + j], b0, b1);
                a0 += bv; a1 += bv; b0 += bv; b1 += bv;
                if (act == 1) {
                    a0 = fmaxf(a0, 0.f); a1 = fmaxf(a1, 0.f);
                    b0 = fmaxf(b0, 0.f); b1 = fmaxf(b1, 0.f);
                } else if (act == 2) {
                    a0 = a0 >= 0.f ? a0 : 0.01f * a0;
                    a1 = a1 >= 0.f ? a1 : 0.01f * a1;
                    b0 = b0 >= 0.f ? b0 : 0.01f * b0;
                    b1 = b1 >= 0.f ? b1 : 0.01f * b1;
                }
                *reinterpret_cast<float2*>(op + 2 * j)      = make_float2(a0, a1);
                *reinterpret_cast<float2*>(op + HW + 2 * j) = make_float2(b0, b1);
            }
        }
    } else {
        const int lane = tid & 31;
        #pragma unroll
        for (int o = 0; o < 4; o++) {
            float m = -FLT_MAX;
            #pragma unroll
            for (int j = 0; j < 4; j++) {
                float a0, a1, b0, b1;
                upk2(accR0[o * 4 + j], a0, a1);
                upk2(accR1[o * 4 + j], b0, b1);
                m = fmaxf(m, fmaxf(fmaxf(a0, a1), fmaxf(b0, b1)));
            }
            #pragma unroll
            for (int d = 16; d; d >>= 1)
                m = fmaxf(m, __shfl_xor_sync(0xffffffffu, m, d));
            if (lane == 0) atomicMaxFloat(&maxout[n * cout + oc0 + o], m);
        }
    }
}

// -------------------- final: bias+lrelu pooled -> 1x1 conv -> softmax --------
__global__ void final_kernel(const float* __restrict__ bw2,
                             const float* __restrict__ ww3,
                             const float* __restrict__ bw3,
                             float* __restrict__ out_w) {
    __shared__ float sp_[CH_MK];
    __shared__ float sv_[CH_MK];
    const int c = threadIdx.x;
    const int n = blockIdx.x;
    float pv = g_pool[n * CH_MK + c] + bw2[c];
    sp_[c] = pv >= 0.f ? pv : 0.01f * pv;
    __syncthreads();
    float sacc = bw3[c];
    const float* wr = ww3 + c * CH_MK;
    for (int i = 0; i < CH_MK; i++) sacc += wr[i] * sp_[i];
    sv_[c] = sacc;
    __syncthreads();
    const int m = c % 192;
    float e0 = sv_[m], e1 = sv_[m + 192], e2 = sv_[m + 384];
    float mx = fmaxf(e0, fmaxf(e1, e2));
    float den = expf(e0 - mx) + expf(e1 - mx) + expf(e2 - mx);
    out_w[n * CH_MK + c] = expf(sv_[c] - mx) / den;
}

// -------------------- launch ------------------------------------------------
extern "C" void kernel_launch(void* const* d_in, const int* in_sizes, int n_in,
                              void* d_out, int out_size) {
    const float* z2  = (const float*)d_in[0];
    const float* y1  = (const float*)d_in[1];
    const float* ws1 = (const float*)d_in[2];  const float* bs1 = (const float*)d_in[3];
    const float* ws2 = (const float*)d_in[4];  const float* bs2 = (const float*)d_in[5];
    const float* ws3 = (const float*)d_in[6];  const float* bs3 = (const float*)d_in[7];
    const float* wm1 = (const float*)d_in[8];  const float* bm1 = (const float*)d_in[9];
    const float* wm2 = (const float*)d_in[10]; const float* bm2 = (const float*)d_in[11];
    const float* wm3 = (const float*)d_in[12]; const float* bm3 = (const float*)d_in[13];
    const float* ww1 = (const float*)d_in[14]; const float* bw1 = (const float*)d_in[15];
    const float* ww2 = (const float*)d_in[16]; const float* bw2 = (const float*)d_in[17];
    const float* ww3 = (const float*)d_in[18]; const float* bw3 = (const float*)d_in[19];

    float* out = (float*)d_out;
    const size_t MEAN_OFF = (size_t)BATCH * CH_MK * HW2;
    const size_t W_OFF    = 2 * MEAN_OFF;

    void* p;
    cudaGetSymbolAddress(&p, g_cat); float* cat = (float*)p;
    cudaGetSymbolAddress(&p, g_t1);  float* t1  = (float*)p;
    cudaGetSymbolAddress(&p, g_t2);  float* t2  = (float*)p;

    cudaFuncSetAttribute(conv5x5_kernel,
                         cudaFuncAttributeMaxDynamicSharedMemorySize, SMEM_TOTAL);

    {
        int total = BATCH * CH_CAT * HW2;
        upsample_concat_kernel<<<(total + 255) / 256, 256>>>(z2, y1);
    }
    init_pool_kernel<<<(BATCH * CH_MK + 255) / 256, 256>>>();

    dim3 blk(256);
    dim3 g128(9, CH_N / 16, BATCH);
    dim3 g576(9, CH_MK / 16, BATCH);

    // sigma branch (relu, relu, relu)
    conv5x5_kernel<<<g128, blk, SMEM_TOTAL>>>(cat, CH_CAT, ws1, bs1, t1, CH_N, 1, nullptr);
    conv5x5_kernel<<<g128, blk, SMEM_TOTAL>>>(t1, CH_N, ws2, bs2, t2, CH_N, 1, nullptr);
    conv5x5_kernel<<<g576, blk, SMEM_TOTAL>>>(t2, CH_N, ws3, bs3, out, CH_MK, 1, nullptr);

    // means branch (lrelu, lrelu, none)
    conv5x5_kernel<<<g128, blk, SMEM_TOTAL>>>(cat, CH_CAT, wm1, bm1, t1, CH_N, 2, nullptr);
    conv5x5_kernel<<<g128, blk, SMEM_TOTAL>>>(t1, CH_N, wm2, bm2, t2, CH_N, 2, nullptr);
    conv5x5_kernel<<<g576, blk, SMEM_TOTAL>>>(t2, CH_N, wm3, bm3, out + MEAN_OFF, CH_MK, 0, nullptr);

    // weights branch (lrelu, then fused max-pool)
    conv5x5_kernel<<<g128, blk, SMEM_TOTAL>>>(cat, CH_CAT, ww1, bw1, t1, CH_N, 2, nullptr);
    {
        void* pp; cudaGetSymbolAddress(&pp, g_pool);
        conv5x5_kernel<<<g576, blk, SMEM_TOTAL>>>(t1, CH_N, ww2, nullptr, nullptr, CH_MK, 0, (float*)pp);
        final_kernel<<<BATCH, CH_MK>>>(bw2, ww3, bw3, out + W_OFF);
    }
}

// round 5
// speedup vs baseline: 3.3736x; 3.1311x over previous
#include <cuda_runtime.h>
#include <cuda_bf16.h>
#include <cfloat>
#include <math.h>
#include <cstdint>

// ---------------------------------------------------------------------------
//   z2: (8,128,24,24)  y1: (8,192,96,96)
//   cat = concat(upsample4x(z2), y1) : (8,320,96,96)
//   sigma = relu(c5(relu(c5(relu(c5(cat,ws1)),ws2)),ws3))        -> (8,576,96,96)
//   means = c5(lrelu(c5(lrelu(c5(cat,wm1)),wm2)),wm3)            -> (8,576,96,96)
//   w     = softmax_K( c1x1( lrelu( maxHW( c5(lrelu(c5(cat,ww1)),ww2) ))))
// Output packing: [sigma | means | weights]
// Conv via mma.sync m16n8k16 bf16 (compute_100-legal), hi/lo split 3-term.
// ---------------------------------------------------------------------------
#define BATCH 8
#define CH_Z 128
#define CH_Y 192
#define CH_CAT 320
#define CH_N 128
#define CH_MK 576
#define HW 96
#define HW2 (HW*HW)

// -------------------- scratch (static device globals; no allocs) ------------
__device__ float    g_cat[BATCH * CH_CAT * HW2];
__device__ float    g_t1 [BATCH * CH_N   * HW2];
__device__ float    g_t2 [BATCH * CH_N   * HW2];
__device__ float    g_pool[BATCH * CH_MK];
__device__ uint32_t g_wT[9420800];          // packed (bf16 hi | lo<<16), [tap][oc][cin]

// wT offsets (u32 elements)
#define O_WS1 0u
#define O_WS2 1024000u
#define O_WS3 1433600u
#define O_WM1 3276800u
#define O_WM2 4300800u
#define O_WM3 4710400u
#define O_WW1 6553600u
#define O_WW2 7577600u

__device__ __forceinline__ uint32_t smem_to_u32(const void* smem_ptr) {
    uint32_t addr;
    asm("{ .reg .u64 tmp; cvta.to.shared.u64 tmp, %1; cvt.u32.u64 %0, tmp; }"
        : "=r"(addr) : "l"(smem_ptr));
    return addr;
}
__device__ __forceinline__ void ldsm4(uint32_t a[4], uint32_t addr) {
    asm volatile("ldmatrix.sync.aligned.m8n8.x4.shared.b16 {%0,%1,%2,%3}, [%4];"
        : "=r"(a[0]), "=r"(a[1]), "=r"(a[2]), "=r"(a[3]) : "r"(addr));
}
__device__ __forceinline__ void mma16816(float c[4], const uint32_t a[4],
                                         const uint32_t b0, const uint32_t b1) {
    asm volatile("mma.sync.aligned.m16n8k16.row.col.f32.bf16.bf16.f32 "
        "{%0,%1,%2,%3}, {%4,%5,%6,%7}, {%8,%9}, {%0,%1,%2,%3};"
        : "+f"(c[0]), "+f"(c[1]), "+f"(c[2]), "+f"(c[3])
        : "r"(a[0]), "r"(a[1]), "r"(a[2]), "r"(a[3]), "r"(b0), "r"(b1));
}
__device__ __forceinline__ void atomicMaxFloat(float* addr, float v) {
    if (v >= 0.0f) atomicMax((int*)addr, __float_as_int(v));
    else           atomicMin((unsigned int*)addr, __float_as_uint(v));
}

// -------------------- weight prep: [oc][cin][tap] f32 -> [tap][oc][cin] u32 --
__global__ void wprep_kernel(const float* __restrict__ w, uint32_t wt_off,
                             int cout, int cin) {
    int d = blockIdx.x * blockDim.x + threadIdx.x;
    int total = cout * cin * 25;
    if (d >= total) return;
    int c   = d % cin;
    int oc  = (d / cin) % cout;
    int tap = d / (cin * cout);
    float v = w[((size_t)oc * cin + c) * 25 + tap];
    __nv_bfloat16 h = __float2bfloat16(v);
    __nv_bfloat16 l = __float2bfloat16(v - __bfloat162float(h));
    uint32_t packed = (uint32_t)(*reinterpret_cast<uint16_t*>(&h))
                    | ((uint32_t)(*reinterpret_cast<uint16_t*>(&l)) << 16);
    g_wT[wt_off + (size_t)d] = packed;
}

// -------------------- upsample + concat -------------------------------------
__global__ void upsample_concat_kernel(const float* __restrict__ z2,
                                       const float* __restrict__ y1) {
    int idx = blockIdx.x * blockDim.x + threadIdx.x;
    const int total = BATCH * CH_CAT * HW2;
    if (idx >= total) return;
    int x = idx % HW;
    int y = (idx / HW) % HW;
    int c = (idx / HW2) % CH_CAT;
    int n = idx / (CH_CAT * HW2);
    if (c >= CH_Z) {
        g_cat[idx] = y1[((n * CH_Y + (c - CH_Z)) * HW + y) * HW + x];
    } else {
        float fy = (float)((double)y * 23.0 / 95.0);
        float fx = (float)((double)x * 23.0 / 95.0);
        int y0 = (int)floorf(fy); int y1i = min(y0 + 1, 23);
        int x0 = (int)floorf(fx); int x1i = min(x0 + 1, 23);
        float wy = fy - (float)y0;
        float wx = fx - (float)x0;
        const float* src = z2 + ((n * CH_Z + c) * 24) * 24;
        float v00 = src[y0 * 24 + x0], v01 = src[y0 * 24 + x1i];
        float v10 = src[y1i * 24 + x0], v11 = src[y1i * 24 + x1i];
        float r0 = v00 * (1.f - wx) + v01 * wx;
        float r1 = v10 * (1.f - wx) + v11 * wx;
        g_cat[idx] = r0 * (1.f - wy) + r1 * wy;
    }
}

__global__ void init_pool_kernel() {
    int i = blockIdx.x * blockDim.x + threadIdx.x;
    if (i < BATCH * CH_MK) g_pool[i] = -FLT_MAX;
}

// ===================== mma.sync conv5x5 ======================================
// CTA: 64 oc x (8 rows x 32 cols). 8 warps, warp = 64 oc x 1 row (32 px).
// K chunks of 16 orig channels -> 32 bf16 k-slots (hi block 0-15, lo 16-31).
// Per tap: 3 MMA sets (A_hi*B_hi, A_lo*B_hi, A_hi*B_lo) with fragment reuse.
#define HHR 12
#define HHC 36
#define NPX (HHR * HHC)        // 432
#define BPITCH 80              // 64B data + 16B pad (conflict-free)
#define APITCH 80
#define A_TAP (64 * APITCH)    // 5120
#define SM_A 0
#define SM_B (5 * A_TAP)       // 25600
#define SMEM_BYTES (SM_B + NPX * BPITCH)   // 60160

__global__ __launch_bounds__(256, 2)
void conv5x5_mma_kernel(const float* __restrict__ in, int cin,
                        const uint32_t* __restrict__ wT,
                        const float* __restrict__ bias,
                        float* __restrict__ out, int cout,
                        int act, float* __restrict__ maxout) {
    extern __shared__ unsigned char sm[];
    const uint32_t smu = smem_to_u32(sm);
    const int tid = threadIdx.x, wid = tid >> 5, lane = tid & 31;
    const int n   = blockIdx.z;
    const int ocb = blockIdx.y * 64;
    const int xb  = (blockIdx.x % 3) * 32;
    const int rb  = (blockIdx.x / 3) * 8;

    float acc[4][4][4];
    #pragma unroll
    for (int m = 0; m < 4; m++)
        #pragma unroll
        for (int j = 0; j < 4; j++)
            #pragma unroll
            for (int q = 0; q < 4; q++) acc[m][j][q] = 0.0f;

    const int nchunks = cin >> 4;
    for (int ch = 0; ch < nchunks; ch++) {
        const int cb = ch << 4;
        __syncthreads();   // previous compute done; B/A buffers reusable

        // ---- stage B: halo patch 12x36, 16 channels, hi/lo split ----
        for (int i = tid; i < NPX * 16; i += 256) {
            int cc = i / NPX;
            int p  = i - cc * NPX;
            int hy = p / HHC, hx = p - hy * HHC;
            int gy = rb + hy - 2, gx = xb + hx - 2;
            float v = 0.0f;
            if ((unsigned)gy < (unsigned)HW && (unsigned)gx < (unsigned)HW)
                v = in[(((size_t)n * cin + cb + cc) * HW + gy) * HW + gx];
            __nv_bfloat16 h = __float2bfloat16(v);
            __nv_bfloat16 l = __float2bfloat16(v - __bfloat162float(h));
            *(uint16_t*)(sm + SM_B + p * BPITCH + cc * 2)      = *(uint16_t*)&h;
            *(uint16_t*)(sm + SM_B + p * BPITCH + cc * 2 + 32) = *(uint16_t*)&l;
        }

        for (int ky = 0; ky < 5; ky++) {
            if (ky > 0) __syncthreads();   // previous ky's A reads done
            // ---- stage A: 5 taps (kx 0..4), 64 oc x 16c packed hi/lo ----
            for (int i = tid; i < 5 * 64 * 16; i += 256) {
                int t   = i >> 10;
                int rem = i & 1023;
                int oc  = rem >> 4;
                int cc  = rem & 15;
                uint32_t v = wT[((size_t)((ky * 5 + t) * cout + ocb + oc)) * cin + cb + cc];
                unsigned char* ab = sm + SM_A + t * A_TAP + oc * APITCH + cc * 2;
                *(uint16_t*)(ab)      = (uint16_t)(v & 0xFFFFu);
                *(uint16_t*)(ab + 32) = (uint16_t)(v >> 16);
            }
            __syncthreads();

            #pragma unroll
            for (int kx = 0; kx < 5; kx++) {
                const uint32_t abase = smu + SM_A + kx * A_TAP
                                     + (lane & 15) * APITCH + ((lane >> 4) << 4);
                const int pbase = (wid + ky) * HHC + kx + (lane >> 2);
                const uint32_t boff0 = SM_B + pbase * BPITCH + (lane & 3) * 4;

                uint32_t a_hi[4][4], a_lo[4][4];
                uint32_t b_hi[4][2];
                #pragma unroll
                for (int m = 0; m < 4; m++)
                    ldsm4(a_hi[m], abase + m * 16 * APITCH);
                #pragma unroll
                for (int j = 0; j < 4; j++) {
                    b_hi[j][0] = *(const uint32_t*)(sm + boff0 + j * 8 * BPITCH);
                    b_hi[j][1] = *(const uint32_t*)(sm + boff0 + j * 8 * BPITCH + 16);
                }
                #pragma unroll
                for (int m = 0; m < 4; m++)
                    #pragma unroll
                    for (int j = 0; j < 4; j++)
                        mma16816(acc[m][j], a_hi[m], b_hi[j][0], b_hi[j][1]);

                #pragma unroll
                for (int m = 0; m < 4; m++)
                    ldsm4(a_lo[m], abase + m * 16 * APITCH + 32);
                #pragma unroll
                for (int m = 0; m < 4; m++)
                    #pragma unroll
                    for (int j = 0; j < 4; j++)
                        mma16816(acc[m][j], a_lo[m], b_hi[j][0], b_hi[j][1]);

                #pragma unroll
                for (int j = 0; j < 4; j++) {
                    b_hi[j][0] = *(const uint32_t*)(sm + boff0 + j * 8 * BPITCH + 32);
                    b_hi[j][1] = *(const uint32_t*)(sm + boff0 + j * 8 * BPITCH + 48);
                }
                #pragma unroll
                for (int m = 0; m < 4; m++)
                    #pragma unroll
                    for (int j = 0; j < 4; j++)
                        mma16816(acc[m][j], a_hi[m], b_hi[j][0], b_hi[j][1]);
            }
        }
    }

    // ===================== epilogue =====================
    const int gy = rb + wid;
    if (maxout == nullptr) {
        #pragma unroll
        for (int m = 0; m < 4; m++) {
            const int oc0 = ocb + m * 16 + (lane >> 2);
            const float b0 = bias[oc0], b1 = bias[oc0 + 8];
            float* r0 = out + (((size_t)n * cout + oc0) * HW + gy) * HW;
            float* r1 = out + (((size_t)n * cout + oc0 + 8) * HW + gy) * HW;
            #pragma unroll
            for (int j = 0; j < 4; j++) {
                const int x = xb + j * 8 + (lane & 3) * 2;
                float v0 = acc[m][j][0] + b0, v1 = acc[m][j][1] + b0;
                float v2 = acc[m][j][2] + b1, v3 = acc[m][j][3] + b1;
                if (act == 1) {
                    v0 = fmaxf(v0, 0.f); v1 = fmaxf(v1, 0.f);
                    v2 = fmaxf(v2, 0.f); v3 = fmaxf(v3, 0.f);
                } else if (act == 2) {
                    v0 = v0 >= 0.f ? v0 : 0.01f * v0;
                    v1 = v1 >= 0.f ? v1 : 0.01f * v1;
                    v2 = v2 >= 0.f ? v2 : 0.01f * v2;
                    v3 = v3 >= 0.f ? v3 : 0.01f * v3;
                }
                *reinterpret_cast<float2*>(r0 + x) = make_float2(v0, v1);
                *reinterpret_cast<float2*>(r1 + x) = make_float2(v2, v3);
            }
        }
    } else {
        #pragma unroll
        for (int m = 0; m < 4; m++) {
            float m0 = -FLT_MAX, m1 = -FLT_MAX;
            #pragma unroll
            for (int j = 0; j < 4; j++) {
                m0 = fmaxf(m0, fmaxf(acc[m][j][0], acc[m][j][1]));
                m1 = fmaxf(m1, fmaxf(acc[m][j][2], acc[m][j][3]));
            }
            #pragma unroll
            for (int d = 1; d < 4; d <<= 1) {
                m0 = fmaxf(m0, __shfl_xor_sync(0xffffffffu, m0, d));
                m1 = fmaxf(m1, __shfl_xor_sync(0xffffffffu, m1, d));
            }
            if ((lane & 3) == 0) {
                const int oc0 = ocb + m * 16 + (lane >> 2);
                atomicMaxFloat(&maxout[n * cout + oc0], m0);
                atomicMaxFloat(&maxout[n * cout + oc0 + 8], m1);
            }
        }
    }
}

// -------------------- final: bias+lrelu pooled -> 1x1 conv -> softmax --------
__global__ void final_kernel(const float* __restrict__ bw2,
                             const float* __restrict__ ww3,
                             const float* __restrict__ bw3,
                             float* __restrict__ out_w) {
    __shared__ float sp_[CH_MK];
    __shared__ float sv_[CH_MK];
    const int c = threadIdx.x;
    const int n = blockIdx.x;
    float pv = g_pool[n * CH_MK + c] + bw2[c];
    sp_[c] = pv >= 0.f ? pv : 0.01f * pv;
    __syncthreads();
    float sacc = bw3[c];
    const float* wr = ww3 + c * CH_MK;
    for (int i = 0; i < CH_MK; i++) sacc += wr[i] * sp_[i];
    sv_[c] = sacc;
    __syncthreads();
    const int m = c % 192;
    float e0 = sv_[m], e1 = sv_[m + 192], e2 = sv_[m + 384];
    float mx = fmaxf(e0, fmaxf(e1, e2));
    float den = expf(e0 - mx) + expf(e1 - mx) + expf(e2 - mx);
    out_w[n * CH_MK + c] = expf(sv_[c] - mx) / den;
}

// -------------------- launch ------------------------------------------------
extern "C" void kernel_launch(void* const* d_in, const int* in_sizes, int n_in,
                              void* d_out, int out_size) {
    const float* z2  = (const float*)d_in[0];
    const float* y1  = (const float*)d_in[1];
    const float* ws1 = (const float*)d_in[2];  const float* bs1 = (const float*)d_in[3];
    const float* ws2 = (const float*)d_in[4];  const float* bs2 = (const float*)d_in[5];
    const float* ws3 = (const float*)d_in[6];  const float* bs3 = (const float*)d_in[7];
    const float* wm1 = (const float*)d_in[8];  const float* bm1 = (const float*)d_in[9];
    const float* wm2 = (const float*)d_in[10]; const float* bm2 = (const float*)d_in[11];
    const float* wm3 = (const float*)d_in[12]; const float* bm3 = (const float*)d_in[13];
    const float* ww1 = (const float*)d_in[14]; const float* bw1 = (const float*)d_in[15];
    const float* ww2 = (const float*)d_in[16]; const float* bw2 = (const float*)d_in[17];
    const float* ww3 = (const float*)d_in[18]; const float* bw3 = (const float*)d_in[19];

    float* out = (float*)d_out;
    const size_t MEAN_OFF = (size_t)BATCH * CH_MK * HW2;
    const size_t W_OFF    = 2 * MEAN_OFF;

    void* p;
    cudaGetSymbolAddress(&p, g_cat); float* cat = (float*)p;
    cudaGetSymbolAddress(&p, g_t1);  float* t1  = (float*)p;
    cudaGetSymbolAddress(&p, g_t2);  float* t2  = (float*)p;
    cudaGetSymbolAddress(&p, g_pool); float* pool = (float*)p;
    cudaGetSymbolAddress(&p, g_wT);  const uint32_t* wT = (const uint32_t*)p;

    cudaFuncSetAttribute(conv5x5_mma_kernel,
                         cudaFuncAttributeMaxDynamicSharedMemorySize, SMEM_BYTES);

    // ---- weight prep (packed hi/lo, [tap][oc][cin]) ----
    auto prep = [&](const float* w, uint32_t off, int cout, int cin) {
        int total = cout * cin * 25;
        wprep_kernel<<<(total + 255) / 256, 256>>>(w, off, cout, cin);
    };
    prep(ws1, O_WS1, CH_N,  CH_CAT);
    prep(ws2, O_WS2, CH_N,  CH_N);
    prep(ws3, O_WS3, CH_MK, CH_N);
    prep(wm1, O_WM1, CH_N,  CH_CAT);
    prep(wm2, O_WM2, CH_N,  CH_N);
    prep(wm3, O_WM3, CH_MK, CH_N);
    prep(ww1, O_WW1, CH_N,  CH_CAT);
    prep(ww2, O_WW2, CH_MK, CH_N);

    {
        int total = BATCH * CH_CAT * HW2;
        upsample_concat_kernel<<<(total + 255) / 256, 256>>>(z2, y1);
    }
    init_pool_kernel<<<(BATCH * CH_MK + 255) / 256, 256>>>();

    dim3 blk(256);
    dim3 g128(36, CH_N / 64, BATCH);      // 36 x 2 x 8
    dim3 g576(36, CH_MK / 64, BATCH);     // 36 x 9 x 8

    // sigma branch (relu, relu, relu)
    conv5x5_mma_kernel<<<g128, blk, SMEM_BYTES>>>(cat, CH_CAT, wT + O_WS1, bs1, t1, CH_N, 1, nullptr);
    conv5x5_mma_kernel<<<g128, blk, SMEM_BYTES>>>(t1, CH_N, wT + O_WS2, bs2, t2, CH_N, 1, nullptr);
    conv5x5_mma_kernel<<<g576, blk, SMEM_BYTES>>>(t2, CH_N, wT + O_WS3, bs3, out, CH_MK, 1, nullptr);

    // means branch (lrelu, lrelu, none)
    conv5x5_mma_kernel<<<g128, blk, SMEM_BYTES>>>(cat, CH_CAT, wT + O_WM1, bm1, t1, CH_N, 2, nullptr);
    conv5x5_mma_kernel<<<g128, blk, SMEM_BYTES>>>(t1, CH_N, wT + O_WM2, bm2, t2, CH_N, 2, nullptr);
    conv5x5_mma_kernel<<<g576, blk, SMEM_BYTES>>>(t2, CH_N, wT + O_WM3, bm3, out + MEAN_OFF, CH_MK, 0, nullptr);

    // weights branch (lrelu, then conv with fused global max)
    conv5x5_mma_kernel<<<g128, blk, SMEM_BYTES>>>(cat, CH_CAT, wT + O_WW1, bw1, t1, CH_N, 2, nullptr);
    conv5x5_mma_kernel<<<g576, blk, SMEM_BYTES>>>(t1, CH_N, wT + O_WW2, nullptr, nullptr, CH_MK, 0, pool);
    final_kernel<<<BATCH, CH_MK>>>(bw2, ww3, bw3, out + W_OFF);
}

// round 6
// speedup vs baseline: 4.4275x; 1.3124x over previous
#include <cuda_runtime.h>
#include <cuda_bf16.h>
#include <cfloat>
#include <math.h>
#include <cstdint>

// ---------------------------------------------------------------------------
//   z2: (8,128,24,24)  y1: (8,192,96,96)
//   cat = concat(upsample4x(z2), y1) : (8,320,96,96)
//   sigma = relu(c5(relu(c5(relu(c5(cat,ws1)),ws2)),ws3))        -> (8,576,96,96)
//   means = c5(lrelu(c5(lrelu(c5(cat,wm1)),wm2)),wm3)            -> (8,576,96,96)
//   w     = softmax_K( c1x1( lrelu( maxHW( c5(lrelu(c5(cat,ww1)),ww2) ))))
// Output packing: [sigma | means | weights]
// Conv via mma.sync m16n8k16 bf16, hi/lo split 3-term; activations+weights kept
// in pre-split packed layout so staging is pure cp.async 16B copies.
// ---------------------------------------------------------------------------
#define BATCH 8
#define CH_Z 128
#define CH_Y 192
#define CH_CAT 320
#define CH_N 128
#define CH_MK 576
#define HW 96
#define HW2 (HW*HW)

// -------------------- scratch (static device globals; no allocs) ------------
// packed activation layout: [n][chunk=c/16][y][x][64B: 16 hi bf16 | 16 lo bf16]
__device__ uint32_t g_cat[BATCH * 20 * HW2 * 16];   // 94.4 MB
__device__ uint32_t g_t1 [BATCH *  8 * HW2 * 16];   // 37.7 MB
__device__ uint32_t g_t2 [BATCH *  8 * HW2 * 16];   // 37.7 MB
__device__ float    g_pool[BATCH * CH_MK];
// weight fmt: per layer: [tap][chunk][oc][64B: 16 hi | 16 lo]
__device__ uint32_t g_wT[9420800];

// wT offsets (u32 elements)
#define O_WS1 0u
#define O_WS2 1024000u
#define O_WS3 1433600u
#define O_WM1 3276800u
#define O_WM2 4300800u
#define O_WM3 4710400u
#define O_WW1 6553600u
#define O_WW2 7577600u

__device__ __forceinline__ uint32_t smem_to_u32(const void* smem_ptr) {
    uint32_t addr;
    asm("{ .reg .u64 tmp; cvta.to.shared.u64 tmp, %1; cvt.u32.u64 %0, tmp; }"
        : "=r"(addr) : "l"(smem_ptr));
    return addr;
}
__device__ __forceinline__ void ldsm4(uint32_t a[4], uint32_t addr) {
    asm volatile("ldmatrix.sync.aligned.m8n8.x4.shared.b16 {%0,%1,%2,%3}, [%4];"
        : "=r"(a[0]), "=r"(a[1]), "=r"(a[2]), "=r"(a[3]) : "r"(addr));
}
__device__ __forceinline__ void mma16816(float c[4], const uint32_t a[4],
                                         const uint32_t b0, const uint32_t b1) {
    asm volatile("mma.sync.aligned.m16n8k16.row.col.f32.bf16.bf16.f32 "
        "{%0,%1,%2,%3}, {%4,%5,%6,%7}, {%8,%9}, {%0,%1,%2,%3};"
        : "+f"(c[0]), "+f"(c[1]), "+f"(c[2]), "+f"(c[3])
        : "r"(a[0]), "r"(a[1]), "r"(a[2]), "r"(a[3]), "r"(b0), "r"(b1));
}
__device__ __forceinline__ void cp16(uint32_t dst, const void* src) {
    asm volatile("cp.async.cg.shared.global [%0], [%1], 16;\n"
        :: "r"(dst), "l"(src));
}
__device__ __forceinline__ void cp16_zfill(uint32_t dst, const void* src) {
    asm volatile("cp.async.cg.shared.global [%0], [%1], 16, 0;\n"
        :: "r"(dst), "l"(src));
}
#define CP_COMMIT asm volatile("cp.async.commit_group;\n" ::: "memory")
#define CP_WAIT0  asm volatile("cp.async.wait_group 0;\n" ::: "memory")

__device__ __forceinline__ void atomicMaxFloat(float* addr, float v) {
    if (v >= 0.0f) atomicMax((int*)addr, __float_as_int(v));
    else           atomicMin((unsigned int*)addr, __float_as_uint(v));
}
__device__ __forceinline__ void split2(float v, uint16_t& h, uint16_t& l) {
    __nv_bfloat16 bh = __float2bfloat16(v);
    __nv_bfloat16 bl = __float2bfloat16(v - __bfloat162float(bh));
    h = *reinterpret_cast<uint16_t*>(&bh);
    l = *reinterpret_cast<uint16_t*>(&bl);
}

// -------------------- fused weight prep --------------------------------------
struct WPack { const float* w[8]; };
// per-layer {cout, cin, out_off(u32), cum_pairs}
__global__ void wprep_all_kernel(WPack wp) {
    const int coutA[8] = {128,128,576,128,128,576,128,576};
    const int cinA [8] = {320,128,128,320,128,128,320,128};
    const uint32_t offA[8] = {O_WS1,O_WS2,O_WS3,O_WM1,O_WM2,O_WM3,O_WW1,O_WW2};
    const uint32_t cum[9] = {0u,512000u,716800u,1638400u,2150400u,2355200u,
                             3276800u,3788800u,4710400u};
    uint32_t d = blockIdx.x * blockDim.x + threadIdx.x;
    if (d >= 4710400u) return;
    int L = 0;
    #pragma unroll
    for (int i = 1; i < 8; i++) if (d >= cum[i]) L = i;
    uint32_t r = d - cum[L];
    const int cout = coutA[L], cin = cinA[L], nch = cin >> 4;
    int cp  = r & 7;
    int oc  = (r >> 3) % cout;
    uint32_t q = (r >> 3) / cout;
    int ch  = q % nch;
    int tap = q / nch;
    int c0  = ch * 16 + cp * 2;
    const float* w = wp.w[L];
    float v0 = w[((size_t)oc * cin + c0) * 25 + tap];
    float v1 = w[((size_t)oc * cin + c0 + 1) * 25 + tap];
    uint16_t h0, l0, h1, l1;
    split2(v0, h0, l0); split2(v1, h1, l1);
    uint32_t base = offA[L] + (((uint32_t)tap * nch + ch) * cout + oc) * 16;
    g_wT[base + cp]     = (uint32_t)h0 | ((uint32_t)h1 << 16);
    g_wT[base + 8 + cp] = (uint32_t)l0 | ((uint32_t)l1 << 16);
}

// -------------------- upsample + concat (packed-split output) ----------------
__global__ void upsample_concat_kernel(const float* __restrict__ z2,
                                       const float* __restrict__ y1) {
    int idx = blockIdx.x * blockDim.x + threadIdx.x;
    const int total = BATCH * CH_CAT * HW2;
    if (idx >= total) return;
    int x = idx % HW;
    int y = (idx / HW) % HW;
    int c = (idx / HW2) % CH_CAT;
    int n = idx / (CH_CAT * HW2);
    float v;
    if (c >= CH_Z) {
        v = y1[((n * CH_Y + (c - CH_Z)) * HW + y) * HW + x];
    } else {
        float fy = (float)((double)y * 23.0 / 95.0);
        float fx = (float)((double)x * 23.0 / 95.0);
        int y0 = (int)floorf(fy); int y1i = min(y0 + 1, 23);
        int x0 = (int)floorf(fx); int x1i = min(x0 + 1, 23);
        float wy = fy - (float)y0;
        float wx = fx - (float)x0;
        const float* src = z2 + ((n * CH_Z + c) * 24) * 24;
        float v00 = src[y0 * 24 + x0], v01 = src[y0 * 24 + x1i];
        float v10 = src[y1i * 24 + x0], v11 = src[y1i * 24 + x1i];
        float r0 = v00 * (1.f - wx) + v01 * wx;
        float r1 = v10 * (1.f - wx) + v11 * wx;
        v = r0 * (1.f - wy) + r1 * wy;
    }
    uint16_t h, l; split2(v, h, l);
    unsigned char* cb = (unsigned char*)g_cat;
    size_t byte = ((((size_t)n * 20 + (c >> 4)) * HW + y) * HW + x) * 64 + (c & 15) * 2;
    *(uint16_t*)(cb + byte)      = h;
    *(uint16_t*)(cb + byte + 32) = l;
}

__global__ void init_pool_kernel() {
    int i = blockIdx.x * blockDim.x + threadIdx.x;
    if (i < BATCH * CH_MK) g_pool[i] = -FLT_MAX;
}

// ===================== mma.sync conv5x5 ======================================
// CTA: 64 oc x (8 rows x 32 cols). 8 warps, warp = 64 oc x 1 row (32 px).
// cp.async staging: B per chunk (16ch), A double-buffered per-ky.
#define HHR 12
#define HHC 36
#define NPX (HHR * HHC)        // 432
#define BPITCH 80
#define APITCH 80
#define A_TAP (64 * APITCH)    // 5120
#define A_BUF (5 * A_TAP)      // 25600
#define SM_A 0
#define SM_B (2 * A_BUF)       // 51200
#define SMEM_BYTES (SM_B + NPX * BPITCH)   // 85760

__global__ __launch_bounds__(256, 2)
void conv5x5_mma_kernel(const unsigned char* __restrict__ in, int cin,
                        const unsigned char* __restrict__ wfmt,
                        const float* __restrict__ bias,
                        void* __restrict__ outp, int cout,
                        int act, int packed_out, float* __restrict__ maxout) {
    extern __shared__ unsigned char sm[];
    const uint32_t smu = smem_to_u32(sm);
    const int tid = threadIdx.x, wid = tid >> 5, lane = tid & 31;
    const int n   = blockIdx.z;
    const int ocb = blockIdx.y * 64;
    const int xb  = (blockIdx.x % 3) * 32;
    const int rb  = (blockIdx.x / 3) * 8;
    const int nch = cin >> 4;

    float acc[4][4][4];
    #pragma unroll
    for (int m = 0; m < 4; m++)
        #pragma unroll
        for (int j = 0; j < 4; j++)
            #pragma unroll
            for (int q = 0; q < 4; q++) acc[m][j][q] = 0.0f;

    for (int ch = 0; ch < nch; ch++) {
        __syncthreads();   // previous chunk's compute done; buffers reusable

        // ---- stage B: 432 halo pixels x 64B ----
        {
            const unsigned char* bb = in + ((size_t)(n * nch + ch) * HW2) * 64;
            for (int i = tid; i < NPX * 4; i += 256) {
                int px = i >> 2, part = i & 3;
                int hy = px / HHC, hx = px - hy * HHC;
                int gy = rb + hy - 2, gx = xb + hx - 2;
                uint32_t dst = smu + SM_B + px * BPITCH + part * 16;
                if ((unsigned)gy < (unsigned)HW && (unsigned)gx < (unsigned)HW)
                    cp16(dst, bb + ((size_t)gy * HW + gx) * 64 + part * 16);
                else
                    cp16_zfill(dst, bb);
            }
        }
        // ---- stage A for ky=0 into buf 0 ----
        {
            const unsigned char* ab = wfmt
                + (((size_t)0 * nch + ch) * cout + ocb) * 64;
            for (int i = tid; i < 1280; i += 256) {
                int part = i & 3, oc = (i >> 2) & 63, t = i >> 8;
                uint32_t dst = smu + SM_A + t * A_TAP + oc * APITCH + part * 16;
                cp16(dst, ab + ((size_t)t * nch * cout + oc) * 64 + part * 16);
            }
        }
        CP_COMMIT; CP_WAIT0; __syncthreads();

        for (int ky = 0; ky < 5; ky++) {
            const int par = ky & 1;
            if (ky < 4) {   // prefetch next ky's A into the other buffer
                const unsigned char* ab = wfmt
                    + (((size_t)(ky + 1) * 5 * nch + ch) * cout + ocb) * 64;
                const uint32_t abuf = smu + SM_A + (par ^ 1) * A_BUF;
                for (int i = tid; i < 1280; i += 256) {
                    int part = i & 3, oc = (i >> 2) & 63, t = i >> 8;
                    uint32_t dst = abuf + t * A_TAP + oc * APITCH + part * 16;
                    cp16(dst, ab + ((size_t)t * nch * cout + oc) * 64 + part * 16);
                }
                CP_COMMIT;
            }

            #pragma unroll
            for (int kx = 0; kx < 5; kx++) {
                const uint32_t abase = smu + SM_A + par * A_BUF + kx * A_TAP
                                     + (lane & 15) * APITCH + ((lane >> 4) << 4);
                const int pbase = (wid + ky) * HHC + kx + (lane >> 2);
                const uint32_t boff0 = SM_B + pbase * BPITCH + (lane & 3) * 4;

                uint32_t a_hi[4][4], a_lo[4][4];
                uint32_t b_f[4][2];
                #pragma unroll
                for (int m = 0; m < 4; m++)
                    ldsm4(a_hi[m], abase + m * 16 * APITCH);
                #pragma unroll
                for (int j = 0; j < 4; j++) {
                    b_f[j][0] = *(const uint32_t*)(sm + boff0 + j * 8 * BPITCH);
                    b_f[j][1] = *(const uint32_t*)(sm + boff0 + j * 8 * BPITCH + 16);
                }
                #pragma unroll
                for (int m = 0; m < 4; m++)
                    #pragma unroll
                    for (int j = 0; j < 4; j++)
                        mma16816(acc[m][j], a_hi[m], b_f[j][0], b_f[j][1]);

                #pragma unroll
                for (int m = 0; m < 4; m++)
                    ldsm4(a_lo[m], abase + m * 16 * APITCH + 32);
                #pragma unroll
                for (int m = 0; m < 4; m++)
                    #pragma unroll
                    for (int j = 0; j < 4; j++)
                        mma16816(acc[m][j], a_lo[m], b_f[j][0], b_f[j][1]);

                #pragma unroll
                for (int j = 0; j < 4; j++) {
                    b_f[j][0] = *(const uint32_t*)(sm + boff0 + j * 8 * BPITCH + 32);
                    b_f[j][1] = *(const uint32_t*)(sm + boff0 + j * 8 * BPITCH + 48);
                }
                #pragma unroll
                for (int m = 0; m < 4; m++)
                    #pragma unroll
                    for (int j = 0; j < 4; j++)
                        mma16816(acc[m][j], a_hi[m], b_f[j][0], b_f[j][1]);
            }

            if (ky < 4) { CP_WAIT0; __syncthreads(); }
        }
    }

    // ===================== epilogue =====================
    const int gy = rb + wid;
    if (maxout != nullptr) {
        #pragma unroll
        for (int m = 0; m < 4; m++) {
            float m0 = -FLT_MAX, m1 = -FLT_MAX;
            #pragma unroll
            for (int j = 0; j < 4; j++) {
                m0 = fmaxf(m0, fmaxf(acc[m][j][0], acc[m][j][1]));
                m1 = fmaxf(m1, fmaxf(acc[m][j][2], acc[m][j][3]));
            }
            #pragma unroll
            for (int d = 1; d < 4; d <<= 1) {
                m0 = fmaxf(m0, __shfl_xor_sync(0xffffffffu, m0, d));
                m1 = fmaxf(m1, __shfl_xor_sync(0xffffffffu, m1, d));
            }
            if ((lane & 3) == 0) {
                const int oc0 = ocb + m * 16 + (lane >> 2);
                atomicMaxFloat(&maxout[n * cout + oc0], m0);
                atomicMaxFloat(&maxout[n * cout + oc0 + 8], m1);
            }
        }
    } else if (packed_out) {
        unsigned char* ob = (unsigned char*)outp;
        const int nchO = cout >> 4;
        #pragma unroll
        for (int m = 0; m < 4; m++) {
            const int ocA = ocb + m * 16 + (lane >> 2);
            const float bA = bias[ocA], bB = bias[ocA + 8];
            const int sA = (ocA & 15) * 2, sB = sA + 16;
            unsigned char* rowb = ob + ((((size_t)n * nchO + (ocA >> 4)) * HW + gy) * HW) * 64;
            #pragma unroll
            for (int j = 0; j < 4; j++) {
                const int x = xb + j * 8 + (lane & 3) * 2;
                float v0 = acc[m][j][0] + bA, v1 = acc[m][j][1] + bA;
                float v2 = acc[m][j][2] + bB, v3 = acc[m][j][3] + bB;
                if (act == 1) {
                    v0 = fmaxf(v0, 0.f); v1 = fmaxf(v1, 0.f);
                    v2 = fmaxf(v2, 0.f); v3 = fmaxf(v3, 0.f);
                } else if (act == 2) {
                    v0 = v0 >= 0.f ? v0 : 0.01f * v0;
                    v1 = v1 >= 0.f ? v1 : 0.01f * v1;
                    v2 = v2 >= 0.f ? v2 : 0.01f * v2;
                    v3 = v3 >= 0.f ? v3 : 0.01f * v3;
                }
                unsigned char* p0 = rowb + (size_t)x * 64;
                uint16_t h, l;
                split2(v0, h, l); *(uint16_t*)(p0 + sA) = h;       *(uint16_t*)(p0 + 32 + sA) = l;
                split2(v1, h, l); *(uint16_t*)(p0 + 64 + sA) = h;  *(uint16_t*)(p0 + 96 + sA) = l;
                split2(v2, h, l); *(uint16_t*)(p0 + sB) = h;       *(uint16_t*)(p0 + 32 + sB) = l;
                split2(v3, h, l); *(uint16_t*)(p0 + 64 + sB) = h;  *(uint16_t*)(p0 + 96 + sB) = l;
            }
        }
    } else {
        float* out = (float*)outp;
        #pragma unroll
        for (int m = 0; m < 4; m++) {
            const int oc0 = ocb + m * 16 + (lane >> 2);
            const float b0 = bias[oc0], b1 = bias[oc0 + 8];
            float* r0 = out + (((size_t)n * cout + oc0) * HW + gy) * HW;
            float* r1 = out + (((size_t)n * cout + oc0 + 8) * HW + gy) * HW;
            #pragma unroll
            for (int j = 0; j < 4; j++) {
                const int x = xb + j * 8 + (lane & 3) * 2;
                float v0 = acc[m][j][0] + b0, v1 = acc[m][j][1] + b0;
                float v2 = acc[m][j][2] + b1, v3 = acc[m][j][3] + b1;
                if (act == 1) {
                    v0 = fmaxf(v0, 0.f); v1 = fmaxf(v1, 0.f);
                    v2 = fmaxf(v2, 0.f); v3 = fmaxf(v3, 0.f);
                } else if (act == 2) {
                    v0 = v0 >= 0.f ? v0 : 0.01f * v0;
                    v1 = v1 >= 0.f ? v1 : 0.01f * v1;
                    v2 = v2 >= 0.f ? v2 : 0.01f * v2;
                    v3 = v3 >= 0.f ? v3 : 0.01f * v3;
                }
                *reinterpret_cast<float2*>(r0 + x) = make_float2(v0, v1);
                *reinterpret_cast<float2*>(r1 + x) = make_float2(v2, v3);
            }
        }
    }
}

// -------------------- final: bias+lrelu pooled -> 1x1 conv -> softmax --------
__global__ void final_kernel(const float* __restrict__ bw2,
                             const float* __restrict__ ww3,
                             const float* __restrict__ bw3,
                             float* __restrict__ out_w) {
    __shared__ float sp_[CH_MK];
    __shared__ float sv_[CH_MK];
    const int c = threadIdx.x;
    const int n = blockIdx.x;
    float pv = g_pool[n * CH_MK + c] + bw2[c];
    sp_[c] = pv >= 0.f ? pv : 0.01f * pv;
    __syncthreads();
    float sacc = bw3[c];
    const float* wr = ww3 + c * CH_MK;
    for (int i = 0; i < CH_MK; i++) sacc += wr[i] * sp_[i];
    sv_[c] = sacc;
    __syncthreads();
    const int m = c % 192;
    float e0 = sv_[m], e1 = sv_[m + 192], e2 = sv_[m + 384];
    float mx = fmaxf(e0, fmaxf(e1, e2));
    float den = expf(e0 - mx) + expf(e1 - mx) + expf(e2 - mx);
    out_w[n * CH_MK + c] = expf(sv_[c] - mx) / den;
}

// -------------------- launch ------------------------------------------------
extern "C" void kernel_launch(void* const* d_in, const int* in_sizes, int n_in,
                              void* d_out, int out_size) {
    const float* z2  = (const float*)d_in[0];
    const float* y1  = (const float*)d_in[1];
    const float* ws1 = (const float*)d_in[2];  const float* bs1 = (const float*)d_in[3];
    const float* ws2 = (const float*)d_in[4];  const float* bs2 = (const float*)d_in[5];
    const float* ws3 = (const float*)d_in[6];  const float* bs3 = (const float*)d_in[7];
    const float* wm1 = (const float*)d_in[8];  const float* bm1 = (const float*)d_in[9];
    const float* wm2 = (const float*)d_in[10]; const float* bm2 = (const float*)d_in[11];
    const float* wm3 = (const float*)d_in[12]; const float* bm3 = (const float*)d_in[13];
    const float* ww1 = (const float*)d_in[14]; const float* bw1 = (const float*)d_in[15];
    const float* ww2 = (const float*)d_in[16]; const float* bw2 = (const float*)d_in[17];
    const float* ww3 = (const float*)d_in[18]; const float* bw3 = (const float*)d_in[19];

    float* out = (float*)d_out;
    const size_t MEAN_OFF = (size_t)BATCH * CH_MK * HW2;
    const size_t W_OFF    = 2 * MEAN_OFF;

    void* p;
    cudaGetSymbolAddress(&p, g_cat); const unsigned char* cat = (const unsigned char*)p;
    cudaGetSymbolAddress(&p, g_t1);  unsigned char* t1 = (unsigned char*)p;
    cudaGetSymbolAddress(&p, g_t2);  unsigned char* t2 = (unsigned char*)p;
    cudaGetSymbolAddress(&p, g_pool); float* pool = (float*)p;
    cudaGetSymbolAddress(&p, g_wT);  const unsigned char* wT = (const unsigned char*)p;

    cudaFuncSetAttribute(conv5x5_mma_kernel,
                         cudaFuncAttributeMaxDynamicSharedMemorySize, SMEM_BYTES);

    // launch 1: fused weight prep
    {
        WPack wp;
        wp.w[0] = ws1; wp.w[1] = ws2; wp.w[2] = ws3;
        wp.w[3] = wm1; wp.w[4] = wm2; wp.w[5] = wm3;
        wp.w[6] = ww1; wp.w[7] = ww2;
        wprep_all_kernel<<<(4710400 + 255) / 256, 256>>>(wp);
    }
    // launch 2: upsample+concat (packed)
    {
        int total = BATCH * CH_CAT * HW2;
        upsample_concat_kernel<<<(total + 255) / 256, 256>>>(z2, y1);
    }
    // launch 3: pool init
    init_pool_kernel<<<(BATCH * CH_MK + 255) / 256, 256>>>();

    dim3 blk(256);
    dim3 g128(36, CH_N / 64, BATCH);      // 36 x 2 x 8
    dim3 g576(36, CH_MK / 64, BATCH);     // 36 x 9 x 8

    const unsigned char* wb = wT;   // byte base

    // sigma branch (relu, relu, relu)  -- launches 4,5,6 (ncu -s 5 captures #6)
    conv5x5_mma_kernel<<<g128, blk, SMEM_BYTES>>>(cat, CH_CAT, wb + (size_t)O_WS1 * 4, bs1, t1, CH_N, 1, 1, nullptr);
    conv5x5_mma_kernel<<<g128, blk, SMEM_BYTES>>>(t1, CH_N, wb + (size_t)O_WS2 * 4, bs2, t2, CH_N, 1, 1, nullptr);
    conv5x5_mma_kernel<<<g576, blk, SMEM_BYTES>>>(t2, CH_N, wb + (size_t)O_WS3 * 4, bs3, out, CH_MK, 1, 0, nullptr);

    // means branch (lrelu, lrelu, none)
    conv5x5_mma_kernel<<<g128, blk, SMEM_BYTES>>>(cat, CH_CAT, wb + (size_t)O_WM1 * 4, bm1, t1, CH_N, 2, 1, nullptr);
    conv5x5_mma_kernel<<<g128, blk, SMEM_BYTES>>>(t1, CH_N, wb + (size_t)O_WM2 * 4, bm2, t2, CH_N, 2, 1, nullptr);
    conv5x5_mma_kernel<<<g576, blk, SMEM_BYTES>>>(t2, CH_N, wb + (size_t)O_WM3 * 4, bm3, out + MEAN_OFF, CH_MK, 0, 0, nullptr);

    // weights branch (lrelu, then conv with fused global max)
    conv5x5_mma_kernel<<<g128, blk, SMEM_BYTES>>>(cat, CH_CAT, wb + (size_t)O_WW1 * 4, bw1, t1, CH_N, 2, 1, nullptr);
    conv5x5_mma_kernel<<<g576, blk, SMEM_BYTES>>>(t1, CH_N, wb + (size_t)O_WW2 * 4, nullptr, nullptr, CH_MK, 0, 0, pool);
    final_kernel<<<BATCH, CH_MK>>>(bw2, ww3, bw3, out + W_OFF);
}

// round 9
// speedup vs baseline: 4.4515x; 1.0054x over previous
#include <cuda_runtime.h>
#include <cuda_bf16.h>
#include <cfloat>
#include <math.h>
#include <cstdint>

// ---------------------------------------------------------------------------
//   z2: (8,128,24,24)  y1: (8,192,96,96)
//   cat = concat(upsample4x(z2), y1) : (8,320,96,96)
//   sigma = relu(c5(relu(c5(relu(c5(cat,ws1)),ws2)),ws3))        -> (8,576,96,96)
//   means = c5(lrelu(c5(lrelu(c5(cat,wm1)),wm2)),wm3)            -> (8,576,96,96)
//   w     = softmax_K( c1x1( lrelu( maxHW( c5(lrelu(c5(cat,ww1)),ww2) ))))
// Output packing: [sigma | means | weights]
// Conv via mma.sync m16n8k16 bf16, hi/lo split 3-term; fully software-pipelined
// cp.async staging; pitch-64 XOR-swizzled smem (16B-aligned, conflict-free).
// ---------------------------------------------------------------------------
#define BATCH 8
#define CH_Z 128
#define CH_Y 192
#define CH_CAT 320
#define CH_N 128
#define CH_MK 576
#define HW 96
#define HW2 (HW*HW)

// -------------------- scratch (static device globals; no allocs) ------------
// packed activation layout: [n][chunk=c/16][y][x][64B: 16 hi bf16 | 16 lo bf16]
__device__ uint32_t g_cat[BATCH * 20 * HW2 * 16];   // 94.4 MB
__device__ uint32_t g_t1 [BATCH *  8 * HW2 * 16];   // 37.7 MB
__device__ uint32_t g_t2 [BATCH *  8 * HW2 * 16];   // 37.7 MB
__device__ float    g_pool[BATCH * CH_MK];
// weight fmt: per layer: [tap][chunk][oc][64B: 16 hi | 16 lo]
__device__ uint32_t g_wT[9420800];

// wT offsets (u32 elements)
#define O_WS1 0u
#define O_WS2 1024000u
#define O_WS3 1433600u
#define O_WM1 3276800u
#define O_WM2 4300800u
#define O_WM3 4710400u
#define O_WW1 6553600u
#define O_WW2 7577600u

__device__ __forceinline__ uint32_t smem_to_u32(const void* smem_ptr) {
    uint32_t addr;
    asm("{ .reg .u64 tmp; cvta.to.shared.u64 tmp, %1; cvt.u32.u64 %0, tmp; }"
        : "=r"(addr) : "l"(smem_ptr));
    return addr;
}
__device__ __forceinline__ void ldsm4(uint32_t a[4], uint32_t addr) {
    asm volatile("ldmatrix.sync.aligned.m8n8.x4.shared.b16 {%0,%1,%2,%3}, [%4];"
        : "=r"(a[0]), "=r"(a[1]), "=r"(a[2]), "=r"(a[3]) : "r"(addr));
}
__device__ __forceinline__ void mma16816(float c[4], const uint32_t a[4],
                                         const uint32_t b0, const uint32_t b1) {
    asm volatile("mma.sync.aligned.m16n8k16.row.col.f32.bf16.bf16.f32 "
        "{%0,%1,%2,%3}, {%4,%5,%6,%7}, {%8,%9}, {%0,%1,%2,%3};"
        : "+f"(c[0]), "+f"(c[1]), "+f"(c[2]), "+f"(c[3])
        : "r"(a[0]), "r"(a[1]), "r"(a[2]), "r"(a[3]), "r"(b0), "r"(b1));
}
__device__ __forceinline__ void cp16(uint32_t dst, const void* src) {
    asm volatile("cp.async.cg.shared.global [%0], [%1], 16;\n"
        :: "r"(dst), "l"(src));
}
__device__ __forceinline__ void cp16_zfill(uint32_t dst, const void* src) {
    asm volatile("cp.async.cg.shared.global [%0], [%1], 16, 0;\n"
        :: "r"(dst), "l"(src));
}
#define CP_COMMIT asm volatile("cp.async.commit_group;\n" ::: "memory")
#define CP_WAIT0  asm volatile("cp.async.wait_group 0;\n" ::: "memory")

__device__ __forceinline__ void atomicMaxFloat(float* addr, float v) {
    if (v >= 0.0f) atomicMax((int*)addr, __float_as_int(v));
    else           atomicMin((unsigned int*)addr, __float_as_uint(v));
}
__device__ __forceinline__ void split2(float v, uint16_t& h, uint16_t& l) {
    __nv_bfloat16 bh = __float2bfloat16(v);
    __nv_bfloat16 bl = __float2bfloat16(v - __bfloat162float(bh));
    h = *reinterpret_cast<uint16_t*>(&bh);
    l = *reinterpret_cast<uint16_t*>(&bl);
}

// -------------------- fused weight prep --------------------------------------
struct WPack { const float* w[8]; };
__global__ void wprep_all_kernel(WPack wp) {
    const int coutA[8] = {128,128,576,128,128,576,128,576};
    const int cinA [8] = {320,128,128,320,128,128,320,128};
    const uint32_t offA[8] = {O_WS1,O_WS2,O_WS3,O_WM1,O_WM2,O_WM3,O_WW1,O_WW2};
    const uint32_t cum[9] = {0u,512000u,716800u,1638400u,2150400u,2355200u,
                             3276800u,3788800u,4710400u};
    uint32_t d = blockIdx.x * blockDim.x + threadIdx.x;
    if (d >= 4710400u) return;
    int L = 0;
    #pragma unroll
    for (int i = 1; i < 8; i++) if (d >= cum[i]) L = i;
    uint32_t r = d - cum[L];
    const int cout = coutA[L], cin = cinA[L], nch = cin >> 4;
    int cp  = r & 7;
    int oc  = (r >> 3) % cout;
    uint32_t q = (r >> 3) / cout;
    int ch  = q % nch;
    int tap = q / nch;
    int c0  = ch * 16 + cp * 2;
    const float* w = wp.w[L];
    float v0 = w[((size_t)oc * cin + c0) * 25 + tap];
    float v1 = w[((size_t)oc * cin + c0 + 1) * 25 + tap];
    uint16_t h0, l0, h1, l1;
    split2(v0, h0, l0); split2(v1, h1, l1);
    uint32_t base = offA[L] + (((uint32_t)tap * nch + ch) * cout + oc) * 16;
    g_wT[base + cp]     = (uint32_t)h0 | ((uint32_t)h1 << 16);
    g_wT[base + 8 + cp] = (uint32_t)l0 | ((uint32_t)l1 << 16);
}

// -------------------- upsample + concat (packed-split output) ----------------
__global__ void upsample_concat_kernel(const float* __restrict__ z2,
                                       const float* __restrict__ y1) {
    int idx = blockIdx.x * blockDim.x + threadIdx.x;
    const int total = BATCH * CH_CAT * HW2;
    if (idx >= total) return;
    int x = idx % HW;
    int y = (idx / HW) % HW;
    int c = (idx / HW2) % CH_CAT;
    int n = idx / (CH_CAT * HW2);
    float v;
    if (c >= CH_Z) {
        v = y1[((n * CH_Y + (c - CH_Z)) * HW + y) * HW + x];
    } else {
        float fy = (float)((double)y * 23.0 / 95.0);
        float fx = (float)((double)x * 23.0 / 95.0);
        int y0 = (int)floorf(fy); int y1i = min(y0 + 1, 23);
        int x0 = (int)floorf(fx); int x1i = min(x0 + 1, 23);
        float wy = fy - (float)y0;
        float wx = fx - (float)x0;
        const float* src = z2 + ((n * CH_Z + c) * 24) * 24;
        float v00 = src[y0 * 24 + x0], v01 = src[y0 * 24 + x1i];
        float v10 = src[y1i * 24 + x0], v11 = src[y1i * 24 + x1i];
        float r0 = v00 * (1.f - wx) + v01 * wx;
        float r1 = v10 * (1.f - wx) + v11 * wx;
        v = r0 * (1.f - wy) + r1 * wy;
    }
    uint16_t h, l; split2(v, h, l);
    unsigned char* cb = (unsigned char*)g_cat;
    size_t byte = ((((size_t)n * 20 + (c >> 4)) * HW + y) * HW + x) * 64 + (c & 15) * 2;
    *(uint16_t*)(cb + byte)      = h;
    *(uint16_t*)(cb + byte + 32) = l;
}

__global__ void init_pool_kernel() {
    int i = blockIdx.x * blockDim.x + threadIdx.x;
    if (i < BATCH * CH_MK) g_pool[i] = -FLT_MAX;
}

// ===================== mma.sync conv5x5 ======================================
// CTA: 64 oc x (8 rows x 32 cols). 8 warps, warp = 64 oc x 1 row (32 px).
// Pipeline: B double-buffered across chunks, A double-buffered per ky;
// next chunk's B + ky0-A prefetched during ky=4 compute.
// smem rows are 64B with XOR swizzle: part p of row r at ((p ^ ((r>>1)&3))<<4).
#define HHR 12
#define HHC 36
#define NPX (HHR * HHC)        // 432
#define BBUF (NPX * 64)        // 27648
#define A_TAP (64 * 64)        // 4096
#define A_BUF (5 * A_TAP)      // 20480
#define SM_A 0
#define SM_B (2 * A_BUF)       // 40960
#define SMEM_BYTES (SM_B + 2 * BBUF)   // 96256

__device__ __forceinline__ uint32_t swz(int row, int part) {
    return (uint32_t)((part ^ ((row >> 1) & 3)) << 4);
}

__global__ __launch_bounds__(256, 2)
void conv5x5_mma_kernel(const unsigned char* __restrict__ in, int cin,
                        const unsigned char* __restrict__ wfmt,
                        const float* __restrict__ bias,
                        void* __restrict__ outp, int cout,
                        int act, int packed_out, float* __restrict__ maxout) {
    extern __shared__ unsigned char sm[];
    const uint32_t smu = smem_to_u32(sm);
    const int tid = threadIdx.x, wid = tid >> 5, lane = tid & 31;
    const int n   = blockIdx.z;
    const int ocb = blockIdx.y * 64;
    const int xb  = (blockIdx.x % 3) * 32;
    const int rb  = (blockIdx.x / 3) * 8;
    const int nch = cin >> 4;

    float acc[4][4][4];
    #pragma unroll
    for (int m = 0; m < 4; m++)
        #pragma unroll
        for (int j = 0; j < 4; j++)
            #pragma unroll
            for (int q = 0; q < 4; q++) acc[m][j][q] = 0.0f;

    // ---- staging helpers ----
    auto stageB = [&](int ch, int buf) {
        const unsigned char* bb = in + ((size_t)(n * nch + ch) * HW2) * 64;
        const uint32_t dstb = smu + SM_B + buf * BBUF;
        for (int i = tid; i < NPX * 4; i += 256) {
            int px = i >> 2, part = i & 3;
            int hy = px / HHC, hx = px - hy * HHC;
            int gy = rb + hy - 2, gx = xb + hx - 2;
            uint32_t dst = dstb + px * 64 + swz(px, part);
            if ((unsigned)gy < (unsigned)HW && (unsigned)gx < (unsigned)HW)
                cp16(dst, bb + ((size_t)gy * HW + gx) * 64 + part * 16);
            else
                cp16_zfill(dst, bb);
        }
    };
    auto stageA = [&](int ch, int ky, int buf) {
        const unsigned char* ab = wfmt + (((size_t)(ky * 5) * nch + ch) * cout + ocb) * 64;
        const uint32_t abuf = smu + SM_A + buf * A_BUF;
        for (int i = tid; i < 1280; i += 256) {
            int part = i & 3, oc = (i >> 2) & 63, t = i >> 8;
            uint32_t dst = abuf + t * A_TAP + oc * 64 + swz(oc, part);
            cp16(dst, ab + ((size_t)t * nch * cout + oc) * 64 + part * 16);
        }
    };

    // ---- preload chunk 0 ----
    int ap = 0, bc = 0;
    stageB(0, 0);
    stageA(0, 0, 0);
    CP_COMMIT; CP_WAIT0; __syncthreads();

    for (int ch = 0; ch < nch; ch++) {
        for (int ky = 0; ky < 5; ky++) {
            // prefetch
            if (ky < 4) {
                stageA(ch, ky + 1, ap ^ 1);
                CP_COMMIT;
            } else if (ch + 1 < nch) {
                stageB(ch + 1, bc ^ 1);
                stageA(ch + 1, 0, ap ^ 1);
                CP_COMMIT;
            }

            // compute ky with A[ap], B[bc]
            #pragma unroll
            for (int kx = 0; kx < 5; kx++) {
                const int arow = lane & 15;
                const int ah   = lane >> 4;          // 0 or 1 (16B column)
                const uint32_t arowb = smu + SM_A + ap * A_BUF + kx * A_TAP + arow * 64;
                const int pbase = (wid + ky) * HHC + kx + (lane >> 2);
                const uint32_t bbufb = SM_B + bc * BBUF;
                const int lc = (lane & 3) * 4;

                uint32_t a_hi[4][4], a_lo[4][4];
                uint32_t b_f[4][2];
                #pragma unroll
                for (int m = 0; m < 4; m++)
                    ldsm4(a_hi[m], arowb + m * 16 * 64 + swz(arow, ah));
                #pragma unroll
                for (int j = 0; j < 4; j++) {
                    int px = pbase + j * 8;
                    const unsigned char* bp = sm + bbufb + px * 64;
                    b_f[j][0] = *(const uint32_t*)(bp + swz(px, 0) + lc);
                    b_f[j][1] = *(const uint32_t*)(bp + swz(px, 1) + lc);
                }
                #pragma unroll
                for (int m = 0; m < 4; m++)
                    #pragma unroll
                    for (int j = 0; j < 4; j++)
                        mma16816(acc[m][j], a_hi[m], b_f[j][0], b_f[j][1]);

                #pragma unroll
                for (int m = 0; m < 4; m++)
                    ldsm4(a_lo[m], arowb + m * 16 * 64 + swz(arow, 2 + ah));
                #pragma unroll
                for (int m = 0; m < 4; m++)
                    #pragma unroll
                    for (int j = 0; j < 4; j++)
                        mma16816(acc[m][j], a_lo[m], b_f[j][0], b_f[j][1]);

                #pragma unroll
                for (int j = 0; j < 4; j++) {
                    int px = pbase + j * 8;
                    const unsigned char* bp = sm + bbufb + px * 64;
                    b_f[j][0] = *(const uint32_t*)(bp + swz(px, 2) + lc);
                    b_f[j][1] = *(const uint32_t*)(bp + swz(px, 3) + lc);
                }
                #pragma unroll
                for (int m = 0; m < 4; m++)
                    #pragma unroll
                    for (int j = 0; j < 4; j++)
                        mma16816(acc[m][j], a_hi[m], b_f[j][0], b_f[j][1]);
            }

            // drain prefetch + make visible (skip after the very last tile)
            if (!(ky == 4 && ch + 1 == nch)) {
                CP_WAIT0; __syncthreads();
            }
            ap ^= 1;
        }
        bc ^= 1;
    }

    // ===================== epilogue =====================
    const int gy = rb + wid;
    if (maxout != nullptr) {
        #pragma unroll
        for (int m = 0; m < 4; m++) {
            float m0 = -FLT_MAX, m1 = -FLT_MAX;
            #pragma unroll
            for (int j = 0; j < 4; j++) {
                m0 = fmaxf(m0, fmaxf(acc[m][j][0], acc[m][j][1]));
                m1 = fmaxf(m1, fmaxf(acc[m][j][2], acc[m][j][3]));
            }
            #pragma unroll
            for (int d = 1; d < 4; d <<= 1) {
                m0 = fmaxf(m0, __shfl_xor_sync(0xffffffffu, m0, d));
                m1 = fmaxf(m1, __shfl_xor_sync(0xffffffffu, m1, d));
            }
            if ((lane & 3) == 0) {
                const int oc0 = ocb + m * 16 + (lane >> 2);
                atomicMaxFloat(&maxout[n * cout + oc0], m0);
                atomicMaxFloat(&maxout[n * cout + oc0 + 8], m1);
            }
        }
    } else if (packed_out) {
        unsigned char* ob = (unsigned char*)outp;
        const int nchO = cout >> 4;
        #pragma unroll
        for (int m = 0; m < 4; m++) {
            const int ocA = ocb + m * 16 + (lane >> 2);
            const float bA = bias[ocA], bB = bias[ocA + 8];
            const int sA = (ocA & 15) * 2, sB = sA + 16;
            unsigned char* rowb = ob + ((((size_t)n * nchO + (ocA >> 4)) * HW + gy) * HW) * 64;
            #pragma unroll
            for (int j = 0; j < 4; j++) {
                const int x = xb + j * 8 + (lane & 3) * 2;
                float v0 = acc[m][j][0] + bA, v1 = acc[m][j][1] + bA;
                float v2 = acc[m][j][2] + bB, v3 = acc[m][j][3] + bB;
                if (act == 1) {
                    v0 = fmaxf(v0, 0.f); v1 = fmaxf(v1, 0.f);
                    v2 = fmaxf(v2, 0.f); v3 = fmaxf(v3, 0.f);
                } else if (act == 2) {
                    v0 = v0 >= 0.f ? v0 : 0.01f * v0;
                    v1 = v1 >= 0.f ? v1 : 0.01f * v1;
                    v2 = v2 >= 0.f ? v2 : 0.01f * v2;
                    v3 = v3 >= 0.f ? v3 : 0.01f * v3;
                }
                unsigned char* p0 = rowb + (size_t)x * 64;
                uint16_t h, l;
                split2(v0, h, l); *(uint16_t*)(p0 + sA) = h;       *(uint16_t*)(p0 + 32 + sA) = l;
                split2(v1, h, l); *(uint16_t*)(p0 + 64 + sA) = h;  *(uint16_t*)(p0 + 96 + sA) = l;
                split2(v2, h, l); *(uint16_t*)(p0 + sB) = h;       *(uint16_t*)(p0 + 32 + sB) = l;
                split2(v3, h, l); *(uint16_t*)(p0 + 64 + sB) = h;  *(uint16_t*)(p0 + 96 + sB) = l;
            }
        }
    } else {
        float* out = (float*)outp;
        #pragma unroll
        for (int m = 0; m < 4; m++) {
            const int oc0 = ocb + m * 16 + (lane >> 2);
            const float b0 = bias[oc0], b1 = bias[oc0 + 8];
            float* r0 = out + (((size_t)n * cout + oc0) * HW + gy) * HW;
            float* r1 = out + (((size_t)n * cout + oc0 + 8) * HW + gy) * HW;
            #pragma unroll
            for (int j = 0; j < 4; j++) {
                const int x = xb + j * 8 + (lane & 3) * 2;
                float v0 = acc[m][j][0] + b0, v1 = acc[m][j][1] + b0;
                float v2 = acc[m][j][2] + b1, v3 = acc[m][j][3] + b1;
                if (act == 1) {
                    v0 = fmaxf(v0, 0.f); v1 = fmaxf(v1, 0.f);
                    v2 = fmaxf(v2, 0.f); v3 = fmaxf(v3, 0.f);
                } else if (act == 2) {
                    v0 = v0 >= 0.f ? v0 : 0.01f * v0;
                    v1 = v1 >= 0.f ? v1 : 0.01f * v1;
                    v2 = v2 >= 0.f ? v2 : 0.01f * v2;
                    v3 = v3 >= 0.f ? v3 : 0.01f * v3;
                }
                *reinterpret_cast<float2*>(r0 + x) = make_float2(v0, v1);
                *reinterpret_cast<float2*>(r1 + x) = make_float2(v2, v3);
            }
        }
    }
}

// -------------------- final: bias+lrelu pooled -> 1x1 conv -> softmax --------
__global__ void final_kernel(const float* __restrict__ bw2,
                             const float* __restrict__ ww3,
                             const float* __restrict__ bw3,
                             float* __restrict__ out_w) {
    __shared__ float sp_[CH_MK];
    __shared__ float sv_[CH_MK];
    const int c = threadIdx.x;
    const int n = blockIdx.x;
    float pv = g_pool[n * CH_MK + c] + bw2[c];
    sp_[c] = pv >= 0.f ? pv : 0.01f * pv;
    __syncthreads();
    float sacc = bw3[c];
    const float* wr = ww3 + c * CH_MK;
    for (int i = 0; i < CH_MK; i++) sacc += wr[i] * sp_[i];
    sv_[c] = sacc;
    __syncthreads();
    const int m = c % 192;
    float e0 = sv_[m], e1 = sv_[m + 192], e2 = sv_[m + 384];
    float mx = fmaxf(e0, fmaxf(e1, e2));
    float den = expf(e0 - mx) + expf(e1 - mx) + expf(e2 - mx);
    out_w[n * CH_MK + c] = expf(sv_[c] - mx) / den;
}

// -------------------- launch ------------------------------------------------
extern "C" void kernel_launch(void* const* d_in, const int* in_sizes, int n_in,
                              void* d_out, int out_size) {
    const float* z2  = (const float*)d_in[0];
    const float* y1  = (const float*)d_in[1];
    const float* ws1 = (const float*)d_in[2];  const float* bs1 = (const float*)d_in[3];
    const float* ws2 = (const float*)d_in[4];  const float* bs2 = (const float*)d_in[5];
    const float* ws3 = (const float*)d_in[6];  const float* bs3 = (const float*)d_in[7];
    const float* wm1 = (const float*)d_in[8];  const float* bm1 = (const float*)d_in[9];
    const float* wm2 = (const float*)d_in[10]; const float* bm2 = (const float*)d_in[11];
    const float* wm3 = (const float*)d_in[12]; const float* bm3 = (const float*)d_in[13];
    const float* ww1 = (const float*)d_in[14]; const float* bw1 = (const float*)d_in[15];
    const float* ww2 = (const float*)d_in[16]; const float* bw2 = (const float*)d_in[17];
    const float* ww3 = (const float*)d_in[18]; const float* bw3 = (const float*)d_in[19];

    float* out = (float*)d_out;
    const size_t MEAN_OFF = (size_t)BATCH * CH_MK * HW2;
    const size_t W_OFF    = 2 * MEAN_OFF;

    void* p;
    cudaGetSymbolAddress(&p, g_cat); const unsigned char* cat = (const unsigned char*)p;
    cudaGetSymbolAddress(&p, g_t1);  unsigned char* t1 = (unsigned char*)p;
    cudaGetSymbolAddress(&p, g_t2);  unsigned char* t2 = (unsigned char*)p;
    cudaGetSymbolAddress(&p, g_pool); float* pool = (float*)p;
    cudaGetSymbolAddress(&p, g_wT);  const unsigned char* wT = (const unsigned char*)p;

    cudaFuncSetAttribute(conv5x5_mma_kernel,
                         cudaFuncAttributeMaxDynamicSharedMemorySize, SMEM_BYTES);

    // launch 1: fused weight prep
    {
        WPack wp;
        wp.w[0] = ws1; wp.w[1] = ws2; wp.w[2] = ws3;
        wp.w[3] = wm1; wp.w[4] = wm2; wp.w[5] = wm3;
        wp.w[6] = ww1; wp.w[7] = ww2;
        wprep_all_kernel<<<(4710400 + 255) / 256, 256>>>(wp);
    }
    // launch 2: upsample+concat (packed)
    {
        int total = BATCH * CH_CAT * HW2;
        upsample_concat_kernel<<<(total + 255) / 256, 256>>>(z2, y1);
    }
    // launch 3: pool init
    init_pool_kernel<<<(BATCH * CH_MK + 255) / 256, 256>>>();

    dim3 blk(256);
    dim3 g128(36, CH_N / 64, BATCH);      // 36 x 2 x 8
    dim3 g576(36, CH_MK / 64, BATCH);     // 36 x 9 x 8

    const unsigned char* wb = wT;   // byte base

    // sigma branch (relu, relu, relu)  -- launches 4,5,6 (ncu -s 5 captures #6)
    conv5x5_mma_kernel<<<g128, blk, SMEM_BYTES>>>(cat, CH_CAT, wb + (size_t)O_WS1 * 4, bs1, t1, CH_N, 1, 1, nullptr);
    conv5x5_mma_kernel<<<g128, blk, SMEM_BYTES>>>(t1, CH_N, wb + (size_t)O_WS2 * 4, bs2, t2, CH_N, 1, 1, nullptr);
    conv5x5_mma_kernel<<<g576, blk, SMEM_BYTES>>>(t2, CH_N, wb + (size_t)O_WS3 * 4, bs3, out, CH_MK, 1, 0, nullptr);

    // means branch (lrelu, lrelu, none)
    conv5x5_mma_kernel<<<g128, blk, SMEM_BYTES>>>(cat, CH_CAT, wb + (size_t)O_WM1 * 4, bm1, t1, CH_N, 2, 1, nullptr);
    conv5x5_mma_kernel<<<g128, blk, SMEM_BYTES>>>(t1, CH_N, wb + (size_t)O_WM2 * 4, bm2, t2, CH_N, 2, 1, nullptr);
    conv5x5_mma_kernel<<<g576, blk, SMEM_BYTES>>>(t2, CH_N, wb + (size_t)O_WM3 * 4, bm3, out + MEAN_OFF, CH_MK, 0, 0, nullptr);

    // weights branch (lrelu, then conv with fused global max)
    conv5x5_mma_kernel<<<g128, blk, SMEM_BYTES>>>(cat, CH_CAT, wb + (size_t)O_WW1 * 4, bw1, t1, CH_N, 2, 1, nullptr);
    conv5x5_mma_kernel<<<g576, blk, SMEM_BYTES>>>(t1, CH_N, wb + (size_t)O_WW2 * 4, nullptr, nullptr, CH_MK, 0, 0, pool);
    final_kernel<<<BATCH, CH_MK>>>(bw2, ww3, bw3, out + W_OFF);
}

// round 10
// speedup vs baseline: 4.5153x; 1.0143x over previous
#include <cuda_runtime.h>
#include <cuda_bf16.h>
#include <cfloat>
#include <math.h>
#include <cstdint>

// ---------------------------------------------------------------------------
//   z2: (8,128,24,24)  y1: (8,192,96,96)
//   cat = concat(upsample4x(z2), y1) : (8,320,96,96)
//   sigma = relu(c5(relu(c5(relu(c5(cat,ws1)),ws2)),ws3))        -> (8,576,96,96)
//   means = c5(lrelu(c5(lrelu(c5(cat,wm1)),wm2)),wm3)            -> (8,576,96,96)
//   w     = softmax_K( c1x1( lrelu( maxHW( c5(lrelu(c5(cat,ww1)),ww2) ))))
// Output packing: [sigma | means | weights]
// Conv via mma.sync m16n8k16 bf16, hi/lo 3-term. Branch-fused launches
// (one conv launch per depth) to eliminate 2-wave tail idle.
// ---------------------------------------------------------------------------
#define BATCH 8
#define CH_Z 128
#define CH_Y 192
#define CH_CAT 320
#define CH_N 128
#define CH_MK 576
#define HW 96
#define HW2 (HW*HW)

// -------------------- scratch (static device globals; no allocs) ------------
// packed activation layout: [n][chunk=c/16][y][x][64B: 16 hi bf16 | 16 lo bf16]
__device__ uint32_t g_cat[BATCH * 20 * HW2 * 16];   // 94.4 MB
__device__ uint32_t g_t1s[BATCH *  8 * HW2 * 16];
__device__ uint32_t g_t1m[BATCH *  8 * HW2 * 16];
__device__ uint32_t g_t1w[BATCH *  8 * HW2 * 16];
__device__ uint32_t g_t2s[BATCH *  8 * HW2 * 16];
__device__ uint32_t g_t2m[BATCH *  8 * HW2 * 16];
__device__ float    g_pool[BATCH * CH_MK];
// weight fmt: per layer: [tap][chunk][oc][64B: 16 hi | 16 lo]
__device__ uint32_t g_wT[9420800];

// wT offsets (u32 elements)
#define O_WS1 0u
#define O_WS2 1024000u
#define O_WS3 1433600u
#define O_WM1 3276800u
#define O_WM2 4300800u
#define O_WM3 4710400u
#define O_WW1 6553600u
#define O_WW2 7577600u

__device__ __forceinline__ uint32_t smem_to_u32(const void* smem_ptr) {
    uint32_t addr;
    asm("{ .reg .u64 tmp; cvta.to.shared.u64 tmp, %1; cvt.u32.u64 %0, tmp; }"
        : "=r"(addr) : "l"(smem_ptr));
    return addr;
}
__device__ __forceinline__ void ldsm4(uint32_t a[4], uint32_t addr) {
    asm volatile("ldmatrix.sync.aligned.m8n8.x4.shared.b16 {%0,%1,%2,%3}, [%4];"
        : "=r"(a[0]), "=r"(a[1]), "=r"(a[2]), "=r"(a[3]) : "r"(addr));
}
__device__ __forceinline__ void mma16816(float c[4], const uint32_t a[4],
                                         const uint32_t b0, const uint32_t b1) {
    asm volatile("mma.sync.aligned.m16n8k16.row.col.f32.bf16.bf16.f32 "
        "{%0,%1,%2,%3}, {%4,%5,%6,%7}, {%8,%9}, {%0,%1,%2,%3};"
        : "+f"(c[0]), "+f"(c[1]), "+f"(c[2]), "+f"(c[3])
        : "r"(a[0]), "r"(a[1]), "r"(a[2]), "r"(a[3]), "r"(b0), "r"(b1));
}
__device__ __forceinline__ void cp16(uint32_t dst, const void* src) {
    asm volatile("cp.async.cg.shared.global [%0], [%1], 16;\n"
        :: "r"(dst), "l"(src));
}
__device__ __forceinline__ void cp16_zfill(uint32_t dst, const void* src) {
    asm volatile("cp.async.cg.shared.global [%0], [%1], 16, 0;\n"
        :: "r"(dst), "l"(src));
}
#define CP_COMMIT asm volatile("cp.async.commit_group;\n" ::: "memory")
#define CP_WAIT0  asm volatile("cp.async.wait_group 0;\n" ::: "memory")

__device__ __forceinline__ void atomicMaxFloat(float* addr, float v) {
    if (v >= 0.0f) atomicMax((int*)addr, __float_as_int(v));
    else           atomicMin((unsigned int*)addr, __float_as_uint(v));
}
__device__ __forceinline__ void split2(float v, uint16_t& h, uint16_t& l) {
    __nv_bfloat16 bh = __float2bfloat16(v);
    __nv_bfloat16 bl = __float2bfloat16(v - __bfloat162float(bh));
    h = *reinterpret_cast<uint16_t*>(&bh);
    l = *reinterpret_cast<uint16_t*>(&bl);
}

// -------------------- fused weight prep --------------------------------------
struct WPack { const float* w[8]; };
__global__ void wprep_all_kernel(WPack wp) {
    const int coutA[8] = {128,128,576,128,128,576,128,576};
    const int cinA [8] = {320,128,128,320,128,128,320,128};
    const uint32_t offA[8] = {O_WS1,O_WS2,O_WS3,O_WM1,O_WM2,O_WM3,O_WW1,O_WW2};
    const uint32_t cum[9] = {0u,512000u,716800u,1638400u,2150400u,2355200u,
                             3276800u,3788800u,4710400u};
    uint32_t d = blockIdx.x * blockDim.x + threadIdx.x;
    if (d >= 4710400u) return;
    int L = 0;
    #pragma unroll
    for (int i = 1; i < 8; i++) if (d >= cum[i]) L = i;
    uint32_t r = d - cum[L];
    const int cout = coutA[L], cin = cinA[L], nch = cin >> 4;
    int cp  = r & 7;
    int oc  = (r >> 3) % cout;
    uint32_t q = (r >> 3) / cout;
    int ch  = q % nch;
    int tap = q / nch;
    int c0  = ch * 16 + cp * 2;
    const float* w = wp.w[L];
    float v0 = w[((size_t)oc * cin + c0) * 25 + tap];
    float v1 = w[((size_t)oc * cin + c0 + 1) * 25 + tap];
    uint16_t h0, l0, h1, l1;
    split2(v0, h0, l0); split2(v1, h1, l1);
    uint32_t base = offA[L] + (((uint32_t)tap * nch + ch) * cout + oc) * 16;
    g_wT[base + cp]     = (uint32_t)h0 | ((uint32_t)h1 << 16);
    g_wT[base + 8 + cp] = (uint32_t)l0 | ((uint32_t)l1 << 16);
}

// -------------------- upsample + concat (packed-split output) ----------------
__global__ void upsample_concat_kernel(const float* __restrict__ z2,
                                       const float* __restrict__ y1) {
    int idx = blockIdx.x * blockDim.x + threadIdx.x;
    const int total = BATCH * CH_CAT * HW2;
    if (idx >= total) return;
    int x = idx % HW;
    int y = (idx / HW) % HW;
    int c = (idx / HW2) % CH_CAT;
    int n = idx / (CH_CAT * HW2);
    float v;
    if (c >= CH_Z) {
        v = y1[((n * CH_Y + (c - CH_Z)) * HW + y) * HW + x];
    } else {
        float fy = (float)((double)y * 23.0 / 95.0);
        float fx = (float)((double)x * 23.0 / 95.0);
        int y0 = (int)floorf(fy); int y1i = min(y0 + 1, 23);
        int x0 = (int)floorf(fx); int x1i = min(x0 + 1, 23);
        float wy = fy - (float)y0;
        float wx = fx - (float)x0;
        const float* src = z2 + ((n * CH_Z + c) * 24) * 24;
        float v00 = src[y0 * 24 + x0], v01 = src[y0 * 24 + x1i];
        float v10 = src[y1i * 24 + x0], v11 = src[y1i * 24 + x1i];
        float r0 = v00 * (1.f - wx) + v01 * wx;
        float r1 = v10 * (1.f - wx) + v11 * wx;
        v = r0 * (1.f - wy) + r1 * wy;
    }
    uint16_t h, l; split2(v, h, l);
    unsigned char* cb = (unsigned char*)g_cat;
    size_t byte = ((((size_t)n * 20 + (c >> 4)) * HW + y) * HW + x) * 64 + (c & 15) * 2;
    *(uint16_t*)(cb + byte)      = h;
    *(uint16_t*)(cb + byte + 32) = l;
}

__global__ void init_pool_kernel() {
    int i = blockIdx.x * blockDim.x + threadIdx.x;
    if (i < BATCH * CH_MK) g_pool[i] = -FLT_MAX;
}

// ===================== mma.sync conv5x5 (fused segments) =====================
// CTA: 64 oc x (8 rows x 32 cols). 8 warps, warp = 64 oc x 1 row (32 px).
// blockIdx.y selects (segment, oc tile). Pipeline as in R9 (passing kernel).
#define HHR 12
#define HHC 36
#define NPX (HHR * HHC)        // 432
#define BBUF (NPX * 64)        // 27648
#define A_TAP (64 * 64)        // 4096
#define A_BUF (5 * A_TAP)      // 20480
#define SM_A 0
#define SM_B (2 * A_BUF)       // 40960
#define SMEM_BYTES (SM_B + 2 * BBUF)   // 96256

__device__ __forceinline__ uint32_t swz(int row, int part) {
    return (uint32_t)((part ^ ((row >> 1) & 3)) << 4);
}

struct Seg {
    const unsigned char* in;
    const unsigned char* w;
    const float* bias;
    void* out;
    float* maxout;
    int cout;
    int ntiles;
    int act;         // 0 none, 1 relu, 2 lrelu
    int packed_out;  // 1: packed hi/lo bf16 layout, 0: fp32 NCHW
};
struct Launch3 {
    Seg s[3];
    int nseg;
    int cin;
};

__global__ __launch_bounds__(256, 2)
void conv5x5_mma_kernel(Launch3 L) {
    extern __shared__ unsigned char sm[];
    const uint32_t smu = smem_to_u32(sm);
    const int tid = threadIdx.x, wid = tid >> 5, lane = tid & 31;
    const int n   = blockIdx.z;
    const int xb  = (blockIdx.x % 3) * 32;
    const int rb  = (blockIdx.x / 3) * 8;
    const int cin = L.cin;
    const int nch = cin >> 4;

    // segment lookup (block-uniform)
    int yt = blockIdx.y, si = 0;
    while (si < L.nseg - 1 && yt >= L.s[si].ntiles) { yt -= L.s[si].ntiles; si++; }
    const unsigned char* in   = L.s[si].in;
    const unsigned char* wfmt = L.s[si].w;
    const float* bias  = L.s[si].bias;
    void*  outp        = L.s[si].out;
    float* maxout      = L.s[si].maxout;
    const int cout     = L.s[si].cout;
    const int act      = L.s[si].act;
    const int packed_out = L.s[si].packed_out;
    const int ocb = yt * 64;

    float acc[4][4][4];
    #pragma unroll
    for (int m = 0; m < 4; m++)
        #pragma unroll
        for (int j = 0; j < 4; j++)
            #pragma unroll
            for (int q = 0; q < 4; q++) acc[m][j][q] = 0.0f;

    // ---- staging helpers ----
    auto stageB = [&](int ch, int buf) {
        const unsigned char* bb = in + ((size_t)(n * nch + ch) * HW2) * 64;
        const uint32_t dstb = smu + SM_B + buf * BBUF;
        for (int i = tid; i < NPX * 4; i += 256) {
            int px = i >> 2, part = i & 3;
            int hy = px / HHC, hx = px - hy * HHC;
            int gy = rb + hy - 2, gx = xb + hx - 2;
            uint32_t dst = dstb + px * 64 + swz(px, part);
            if ((unsigned)gy < (unsigned)HW && (unsigned)gx < (unsigned)HW)
                cp16(dst, bb + ((size_t)gy * HW + gx) * 64 + part * 16);
            else
                cp16_zfill(dst, bb);
        }
    };
    auto stageA = [&](int ch, int ky, int buf) {
        const unsigned char* ab = wfmt + (((size_t)(ky * 5) * nch + ch) * cout + ocb) * 64;
        const uint32_t abuf = smu + SM_A + buf * A_BUF;
        for (int i = tid; i < 1280; i += 256) {
            int part = i & 3, oc = (i >> 2) & 63, t = i >> 8;
            uint32_t dst = abuf + t * A_TAP + oc * 64 + swz(oc, part);
            cp16(dst, ab + ((size_t)t * nch * cout + oc) * 64 + part * 16);
        }
    };

    // ---- preload chunk 0 ----
    int ap = 0, bc = 0;
    stageB(0, 0);
    stageA(0, 0, 0);
    CP_COMMIT; CP_WAIT0; __syncthreads();

    for (int ch = 0; ch < nch; ch++) {
        for (int ky = 0; ky < 5; ky++) {
            // prefetch
            if (ky < 4) {
                stageA(ch, ky + 1, ap ^ 1);
                CP_COMMIT;
            } else if (ch + 1 < nch) {
                stageB(ch + 1, bc ^ 1);
                stageA(ch + 1, 0, ap ^ 1);
                CP_COMMIT;
            }

            // compute ky with A[ap], B[bc]
            #pragma unroll
            for (int kx = 0; kx < 5; kx++) {
                const int arow = lane & 15;
                const int ah   = lane >> 4;          // 0 or 1 (16B column)
                const uint32_t arowb = smu + SM_A + ap * A_BUF + kx * A_TAP + arow * 64;
                const int pbase = (wid + ky) * HHC + kx + (lane >> 2);
                const uint32_t bbufb = SM_B + bc * BBUF;
                const int lc = (lane & 3) * 4;

                uint32_t a_hi[4][4], a_lo[4][4];
                uint32_t b_f[4][2];
                #pragma unroll
                for (int m = 0; m < 4; m++)
                    ldsm4(a_hi[m], arowb + m * 16 * 64 + swz(arow, ah));
                #pragma unroll
                for (int j = 0; j < 4; j++) {
                    int px = pbase + j * 8;
                    const unsigned char* bp = sm + bbufb + px * 64;
                    b_f[j][0] = *(const uint32_t*)(bp + swz(px, 0) + lc);
                    b_f[j][1] = *(const uint32_t*)(bp + swz(px, 1) + lc);
                }
                #pragma unroll
                for (int m = 0; m < 4; m++)
                    #pragma unroll
                    for (int j = 0; j < 4; j++)
                        mma16816(acc[m][j], a_hi[m], b_f[j][0], b_f[j][1]);

                #pragma unroll
                for (int m = 0; m < 4; m++)
                    ldsm4(a_lo[m], arowb + m * 16 * 64 + swz(arow, 2 + ah));
                #pragma unroll
                for (int m = 0; m < 4; m++)
                    #pragma unroll
                    for (int j = 0; j < 4; j++)
                        mma16816(acc[m][j], a_lo[m], b_f[j][0], b_f[j][1]);

                #pragma unroll
                for (int j = 0; j < 4; j++) {
                    int px = pbase + j * 8;
                    const unsigned char* bp = sm + bbufb + px * 64;
                    b_f[j][0] = *(const uint32_t*)(bp + swz(px, 2) + lc);
                    b_f[j][1] = *(const uint32_t*)(bp + swz(px, 3) + lc);
                }
                #pragma unroll
                for (int m = 0; m < 4; m++)
                    #pragma unroll
                    for (int j = 0; j < 4; j++)
                        mma16816(acc[m][j], a_hi[m], b_f[j][0], b_f[j][1]);
            }

            // drain prefetch + make visible (skip after the very last tile)
            if (!(ky == 4 && ch + 1 == nch)) {
                CP_WAIT0; __syncthreads();
            }
            ap ^= 1;
        }
        bc ^= 1;
    }

    // ===================== epilogue =====================
    const int gy = rb + wid;
    if (maxout != nullptr) {
        #pragma unroll
        for (int m = 0; m < 4; m++) {
            float m0 = -FLT_MAX, m1 = -FLT_MAX;
            #pragma unroll
            for (int j = 0; j < 4; j++) {
                m0 = fmaxf(m0, fmaxf(acc[m][j][0], acc[m][j][1]));
                m1 = fmaxf(m1, fmaxf(acc[m][j][2], acc[m][j][3]));
            }
            #pragma unroll
            for (int d = 1; d < 4; d <<= 1) {
                m0 = fmaxf(m0, __shfl_xor_sync(0xffffffffu, m0, d));
                m1 = fmaxf(m1, __shfl_xor_sync(0xffffffffu, m1, d));
            }
            if ((lane & 3) == 0) {
                const int oc0 = ocb + m * 16 + (lane >> 2);
                atomicMaxFloat(&maxout[n * cout + oc0], m0);
                atomicMaxFloat(&maxout[n * cout + oc0 + 8], m1);
            }
        }
    } else if (packed_out) {
        unsigned char* ob = (unsigned char*)outp;
        const int nchO = cout >> 4;
        #pragma unroll
        for (int m = 0; m < 4; m++) {
            const int ocA = ocb + m * 16 + (lane >> 2);
            const float bA = bias[ocA], bB = bias[ocA + 8];
            const int sA = (ocA & 15) * 2, sB = sA + 16;
            unsigned char* rowb = ob + ((((size_t)n * nchO + (ocA >> 4)) * HW + gy) * HW) * 64;
            #pragma unroll
            for (int j = 0; j < 4; j++) {
                const int x = xb + j * 8 + (lane & 3) * 2;
                float v0 = acc[m][j][0] + bA, v1 = acc[m][j][1] + bA;
                float v2 = acc[m][j][2] + bB, v3 = acc[m][j][3] + bB;
                if (act == 1) {
                    v0 = fmaxf(v0, 0.f); v1 = fmaxf(v1, 0.f);
                    v2 = fmaxf(v2, 0.f); v3 = fmaxf(v3, 0.f);
                } else if (act == 2) {
                    v0 = v0 >= 0.f ? v0 : 0.01f * v0;
                    v1 = v1 >= 0.f ? v1 : 0.01f * v1;
                    v2 = v2 >= 0.f ? v2 : 0.01f * v2;
                    v3 = v3 >= 0.f ? v3 : 0.01f * v3;
                }
                unsigned char* p0 = rowb + (size_t)x * 64;
                uint16_t h, l;
                split2(v0, h, l); *(uint16_t*)(p0 + sA) = h;       *(uint16_t*)(p0 + 32 + sA) = l;
                split2(v1, h, l); *(uint16_t*)(p0 + 64 + sA) = h;  *(uint16_t*)(p0 + 96 + sA) = l;
                split2(v2, h, l); *(uint16_t*)(p0 + sB) = h;       *(uint16_t*)(p0 + 32 + sB) = l;
                split2(v3, h, l); *(uint16_t*)(p0 + 64 + sB) = h;  *(uint16_t*)(p0 + 96 + sB) = l;
            }
        }
    } else {
        float* out = (float*)outp;
        #pragma unroll
        for (int m = 0; m < 4; m++) {
            const int oc0 = ocb + m * 16 + (lane >> 2);
            const float b0 = bias[oc0], b1 = bias[oc0 + 8];
            float* r0 = out + (((size_t)n * cout + oc0) * HW + gy) * HW;
            float* r1 = out + (((size_t)n * cout + oc0 + 8) * HW + gy) * HW;
            #pragma unroll
            for (int j = 0; j < 4; j++) {
                const int x = xb + j * 8 + (lane & 3) * 2;
                float v0 = acc[m][j][0] + b0, v1 = acc[m][j][1] + b0;
                float v2 = acc[m][j][2] + b1, v3 = acc[m][j][3] + b1;
                if (act == 1) {
                    v0 = fmaxf(v0, 0.f); v1 = fmaxf(v1, 0.f);
                    v2 = fmaxf(v2, 0.f); v3 = fmaxf(v3, 0.f);
                } else if (act == 2) {
                    v0 = v0 >= 0.f ? v0 : 0.01f * v0;
                    v1 = v1 >= 0.f ? v1 : 0.01f * v1;
                    v2 = v2 >= 0.f ? v2 : 0.01f * v2;
                    v3 = v3 >= 0.f ? v3 : 0.01f * v3;
                }
                *reinterpret_cast<float2*>(r0 + x) = make_float2(v0, v1);
                *reinterpret_cast<float2*>(r1 + x) = make_float2(v2, v3);
            }
        }
    }
}

// -------------------- final: bias+lrelu pooled -> 1x1 conv -> softmax --------
__global__ void final_kernel(const float* __restrict__ bw2,
                             const float* __restrict__ ww3,
                             const float* __restrict__ bw3,
                             float* __restrict__ out_w) {
    __shared__ float sp_[CH_MK];
    __shared__ float sv_[CH_MK];
    const int c = threadIdx.x;
    const int n = blockIdx.x;
    float pv = g_pool[n * CH_MK + c] + bw2[c];
    sp_[c] = pv >= 0.f ? pv : 0.01f * pv;
    __syncthreads();
    float sacc = bw3[c];
    const float* wr = ww3 + c * CH_MK;
    for (int i = 0; i < CH_MK; i++) sacc += wr[i] * sp_[i];
    sv_[c] = sacc;
    __syncthreads();
    const int m = c % 192;
    float e0 = sv_[m], e1 = sv_[m + 192], e2 = sv_[m + 384];
    float mx = fmaxf(e0, fmaxf(e1, e2));
    float den = expf(e0 - mx) + expf(e1 - mx) + expf(e2 - mx);
    out_w[n * CH_MK + c] = expf(sv_[c] - mx) / den;
}

// -------------------- launch ------------------------------------------------
extern "C" void kernel_launch(void* const* d_in, const int* in_sizes, int n_in,
                              void* d_out, int out_size) {
    const float* z2  = (const float*)d_in[0];
    const float* y1  = (const float*)d_in[1];
    const float* ws1 = (const float*)d_in[2];  const float* bs1 = (const float*)d_in[3];
    const float* ws2 = (const float*)d_in[4];  const float* bs2 = (const float*)d_in[5];
    const float* ws3 = (const float*)d_in[6];  const float* bs3 = (const float*)d_in[7];
    const float* wm1 = (const float*)d_in[8];  const float* bm1 = (const float*)d_in[9];
    const float* wm2 = (const float*)d_in[10]; const float* bm2 = (const float*)d_in[11];
    const float* wm3 = (const float*)d_in[12]; const float* bm3 = (const float*)d_in[13];
    const float* ww1 = (const float*)d_in[14]; const float* bw1 = (const float*)d_in[15];
    const float* ww2 = (const float*)d_in[16]; const float* bw2 = (const float*)d_in[17];
    const float* ww3 = (const float*)d_in[18]; const float* bw3 = (const float*)d_in[19];

    float* out = (float*)d_out;
    const size_t MEAN_OFF = (size_t)BATCH * CH_MK * HW2;
    const size_t W_OFF    = 2 * MEAN_OFF;

    void* p;
    cudaGetSymbolAddress(&p, g_cat); unsigned char* cat = (unsigned char*)p;
    cudaGetSymbolAddress(&p, g_t1s); unsigned char* t1s = (unsigned char*)p;
    cudaGetSymbolAddress(&p, g_t1m); unsigned char* t1m = (unsigned char*)p;
    cudaGetSymbolAddress(&p, g_t1w); unsigned char* t1w = (unsigned char*)p;
    cudaGetSymbolAddress(&p, g_t2s); unsigned char* t2s = (unsigned char*)p;
    cudaGetSymbolAddress(&p, g_t2m); unsigned char* t2m = (unsigned char*)p;
    cudaGetSymbolAddress(&p, g_pool); float* pool = (float*)p;
    cudaGetSymbolAddress(&p, g_wT);  unsigned char* wb = (unsigned char*)p;

    cudaFuncSetAttribute(conv5x5_mma_kernel,
                         cudaFuncAttributeMaxDynamicSharedMemorySize, SMEM_BYTES);

    // launch 1: fused weight prep
    {
        WPack wp;
        wp.w[0] = ws1; wp.w[1] = ws2; wp.w[2] = ws3;
        wp.w[3] = wm1; wp.w[4] = wm2; wp.w[5] = wm3;
        wp.w[6] = ww1; wp.w[7] = ww2;
        wprep_all_kernel<<<(4710400 + 255) / 256, 256>>>(wp);
    }
    // launch 2: upsample+concat (packed)
    {
        int total = BATCH * CH_CAT * HW2;
        upsample_concat_kernel<<<(total + 255) / 256, 256>>>(z2, y1);
    }
    // launch 3: pool init
    init_pool_kernel<<<(BATCH * CH_MK + 255) / 256, 256>>>();

    dim3 blk(256);

    // launch 4: layer 1 (cat -> t1s/t1m/t1w), cin=320, 6 tiles
    {
        Launch3 L{};
        L.nseg = 3; L.cin = CH_CAT;
        L.s[0] = { cat, wb + (size_t)O_WS1 * 4, bs1, t1s, nullptr, CH_N, 2, 1, 1 };
        L.s[1] = { cat, wb + (size_t)O_WM1 * 4, bm1, t1m, nullptr, CH_N, 2, 2, 1 };
        L.s[2] = { cat, wb + (size_t)O_WW1 * 4, bw1, t1w, nullptr, CH_N, 2, 2, 1 };
        conv5x5_mma_kernel<<<dim3(36, 6, BATCH), blk, SMEM_BYTES>>>(L);
    }
    // launch 5: layer 2 (t1s->t2s, t1m->t2m, t1w->pool), cin=128, 13 tiles
    {
        Launch3 L{};
        L.nseg = 3; L.cin = CH_N;
        L.s[0] = { t1s, wb + (size_t)O_WS2 * 4, bs2, t2s, nullptr, CH_N, 2, 1, 1 };
        L.s[1] = { t1m, wb + (size_t)O_WM2 * 4, bm2, t2m, nullptr, CH_N, 2, 2, 1 };
        L.s[2] = { t1w, wb + (size_t)O_WW2 * 4, nullptr, nullptr, pool, CH_MK, 9, 0, 0 };
        conv5x5_mma_kernel<<<dim3(36, 13, BATCH), blk, SMEM_BYTES>>>(L);
    }
    // launch 6: layer 3 (t2s->sigma, t2m->means), cin=128, 18 tiles
    {
        Launch3 L{};
        L.nseg = 2; L.cin = CH_N;
        L.s[0] = { t2s, wb + (size_t)O_WS3 * 4, bs3, out, nullptr, CH_MK, 9, 1, 0 };
        L.s[1] = { t2m, wb + (size_t)O_WM3 * 4, bm3, out + MEAN_OFF, nullptr, CH_MK, 9, 0, 0 };
        conv5x5_mma_kernel<<<dim3(36, 18, BATCH), blk, SMEM_BYTES>>>(L);
    }
    // launch 7: final softmax head
    final_kernel<<<BATCH, CH_MK>>>(bw2, ww3, bw3, out + W_OFF);
}